// round 1
// baseline (speedup 1.0000x reference)
#include <cuda_runtime.h>

#define N_NODES 8192
#define F_IN    256
#define F_OUT   128

// Scratch (device globals: no allocation allowed in kernel_launch)
__device__ float g_h[N_NODES * F_OUT];   // h = x@W, tf32-rounded, row-major
__device__ float g_src[N_NODES];
__device__ float g_dst[N_NODES];

__device__ __forceinline__ float to_tf32(float v) {
    unsigned r;
    asm("cvt.rna.tf32.f32 %0, %1;" : "=r"(r) : "f"(v));
    return __uint_as_float(r);
}

__device__ __forceinline__ void mma_tf32(float* d, const unsigned* a, const unsigned* b) {
    asm volatile(
        "mma.sync.aligned.m16n8k8.row.col.f32.tf32.tf32.f32 "
        "{%0,%1,%2,%3}, {%4,%5,%6,%7}, {%8,%9}, {%0,%1,%2,%3};\n"
        : "+f"(d[0]), "+f"(d[1]), "+f"(d[2]), "+f"(d[3])
        : "r"(a[0]), "r"(a[1]), "r"(a[2]), "r"(a[3]), "r"(b[0]), "r"(b[1]));
}

// ---------------------------------------------------------------------------
// Kernel 1: h = x@W (fp32 exact), src = h@a1, dst = h@a2, store h tf32-rounded
// grid 128, block 256, 64 rows/block
// ---------------------------------------------------------------------------
__global__ void __launch_bounds__(256, 1)
prep_kernel(const float* __restrict__ x, const float* __restrict__ W,
            const float* __restrict__ a) {
    extern __shared__ float sm[];
    float* W_s = sm;                       // [256][128]
    float* x_s = sm + F_IN * F_OUT;        // [32][260] padded
    const int XS = 260;

    const int t  = threadIdx.x;
    const int tx = t & 15, ty = t >> 4;

    // Load W (coalesced, 128 KB)
    for (int i = t; i < F_IN * F_OUT / 4; i += 256)
        ((float4*)W_s)[i] = ((const float4*)W)[i];

    // Per-thread columns: {4tx..4tx+3} and {64+4tx..64+4tx+3}
    float a1v[8], a2v[8];
    #pragma unroll
    for (int e = 0; e < 4; e++) {
        a1v[e]     = a[4 * tx + e];
        a1v[4 + e] = a[64 + 4 * tx + e];
        a2v[e]     = a[F_OUT + 4 * tx + e];
        a2v[4 + e] = a[F_OUT + 64 + 4 * tx + e];
    }

    const int r0 = blockIdx.x * 64;
    for (int iter = 0; iter < 2; iter++) {
        __syncthreads();
        const int rbase = r0 + iter * 32;
        // Stage 32 rows of x (32 KB)
        for (int i = t; i < 32 * 64; i += 256) {
            int r = i >> 6, c4 = i & 63;
            float4 v = *(const float4*)&x[(rbase + r) * F_IN + c4 * 4];
            *(float4*)&x_s[r * XS + c4 * 4] = v;
        }
        __syncthreads();

        float acc0[8], acc1[8];
        #pragma unroll
        for (int e = 0; e < 8; e++) { acc0[e] = 0.f; acc1[e] = 0.f; }

        #pragma unroll 8
        for (int k = 0; k < F_IN; k++) {
            float xa = x_s[ty * XS + k];
            float xb = x_s[(ty + 16) * XS + k];
            float4 w0 = *(const float4*)&W_s[k * F_OUT + 4 * tx];
            float4 w1 = *(const float4*)&W_s[k * F_OUT + 64 + 4 * tx];
            float wv[8] = {w0.x, w0.y, w0.z, w0.w, w1.x, w1.y, w1.z, w1.w};
            #pragma unroll
            for (int e = 0; e < 8; e++) {
                acc0[e] += xa * wv[e];
                acc1[e] += xb * wv[e];
            }
        }

        // src/dst partials (exact h) + 16-lane reduction
        float sa = 0.f, da = 0.f, sb = 0.f, db = 0.f;
        #pragma unroll
        for (int e = 0; e < 8; e++) {
            sa += acc0[e] * a1v[e];  da += acc0[e] * a2v[e];
            sb += acc1[e] * a1v[e];  db += acc1[e] * a2v[e];
        }
        #pragma unroll
        for (int o = 8; o; o >>= 1) {
            sa += __shfl_down_sync(0xffffffffu, sa, o, 16);
            da += __shfl_down_sync(0xffffffffu, da, o, 16);
            sb += __shfl_down_sync(0xffffffffu, sb, o, 16);
            db += __shfl_down_sync(0xffffffffu, db, o, 16);
        }
        const int ra = rbase + ty, rb = rbase + ty + 16;
        if (tx == 0) {
            g_src[ra] = sa; g_dst[ra] = da;
            g_src[rb] = sb; g_dst[rb] = db;
        }

        // Store h tf32-rounded (MMA B operand)
        float4 oa0, oa1, ob0, ob1;
        oa0.x = to_tf32(acc0[0]); oa0.y = to_tf32(acc0[1]); oa0.z = to_tf32(acc0[2]); oa0.w = to_tf32(acc0[3]);
        oa1.x = to_tf32(acc0[4]); oa1.y = to_tf32(acc0[5]); oa1.z = to_tf32(acc0[6]); oa1.w = to_tf32(acc0[7]);
        ob0.x = to_tf32(acc1[0]); ob0.y = to_tf32(acc1[1]); ob0.z = to_tf32(acc1[2]); ob0.w = to_tf32(acc1[3]);
        ob1.x = to_tf32(acc1[4]); ob1.y = to_tf32(acc1[5]); ob1.z = to_tf32(acc1[6]); ob1.w = to_tf32(acc1[7]);
        *(float4*)&g_h[ra * F_OUT + 4 * tx]      = oa0;
        *(float4*)&g_h[ra * F_OUT + 64 + 4 * tx] = oa1;
        *(float4*)&g_h[rb * F_OUT + 4 * tx]      = ob0;
        *(float4*)&g_h[rb * F_OUT + 64 + 4 * tx] = ob1;
    }
}

// ---------------------------------------------------------------------------
// Kernel 2: fused masked-softmax attention, out = (P @ h) / rowsum(P)
// P_ij = adj ? exp(leaky_relu(src_i + dst_j)) : 0   (shift-free softmax, exact)
// grid 128 (64 rows each), block 256. tf32 mma.sync, j-chunks of 128.
// ---------------------------------------------------------------------------
__global__ void __launch_bounds__(256, 1)
attn_kernel(const int* __restrict__ adj, float* __restrict__ out) {
    extern __shared__ float sm[];
    const int PS = 132, HS = 136;          // padded strides (bank-conflict aware)
    float* P_s = sm;                        // [64][132] tf32 scores
    float* h_s = sm + 64 * PS;              // [128][136] h tile
    float* l_s = h_s + 128 * HS;            // [64] row sums

    const int t   = threadIdx.x;
    const int r0  = blockIdx.x * 64;
    const int row = t >> 2, q = t & 3;      // score phase: 4 threads/row
    const int lane = t & 31, gID = lane >> 2, tig = lane & 3;
    const int w  = t >> 5;
    const int mb = (w & 1) * 32, nb = (w >> 1) * 32;   // warp tile m32 x n32

    const float srcv = g_src[r0 + row];
    float l_reg = 0.f;

    float acc[2][4][4];
    #pragma unroll
    for (int mt = 0; mt < 2; mt++)
        #pragma unroll
        for (int nt = 0; nt < 4; nt++)
            #pragma unroll
            for (int c = 0; c < 4; c++) acc[mt][nt][c] = 0.f;

    const int* adj_row = adj + (r0 + row) * N_NODES + q * 4;
    int4 adjv[8];
    #pragma unroll
    for (int i = 0; i < 8; i++)
        adjv[i] = *(const int4*)&adj_row[i * 16];

    for (int ch = 0; ch < 64; ch++) {
        const int j0 = ch * 128;
        __syncthreads();   // previous mma done with P_s / h_s

        // Stage h tile [128 x 128] (L2-hot after first wave)
        #pragma unroll 4
        for (int u = 0; u < 16; u++) {
            int idx = t + u * 256;
            int jr = idx >> 5, c4 = idx & 31;
            float4 v = *(const float4*)&g_h[(j0 + jr) * F_OUT + c4 * 4];
            *(float4*)&h_s[jr * HS + c4 * 4] = v;
        }

        // Score phase: 32 cols per thread at {4q + 16i + e}
        float lsum = 0.f;
        #pragma unroll
        for (int i = 0; i < 8; i++) {
            const int cb = q * 4 + i * 16;
            int4 av = adjv[i];
            float4 dv = *(const float4*)&g_dst[j0 + cb];
            float4 pv;
            float s;
            s = srcv + dv.x; s = fmaxf(s, 0.2f * s); s = fminf(s, 80.f);
            pv.x = (av.x > 0) ? to_tf32(__expf(s)) : 0.f;
            s = srcv + dv.y; s = fmaxf(s, 0.2f * s); s = fminf(s, 80.f);
            pv.y = (av.y > 0) ? to_tf32(__expf(s)) : 0.f;
            s = srcv + dv.z; s = fmaxf(s, 0.2f * s); s = fminf(s, 80.f);
            pv.z = (av.z > 0) ? to_tf32(__expf(s)) : 0.f;
            s = srcv + dv.w; s = fmaxf(s, 0.2f * s); s = fminf(s, 80.f);
            pv.w = (av.w > 0) ? to_tf32(__expf(s)) : 0.f;
            lsum += (pv.x + pv.y) + (pv.z + pv.w);
            *(float4*)&P_s[row * PS + cb] = pv;
        }
        lsum += __shfl_xor_sync(0xffffffffu, lsum, 1);
        lsum += __shfl_xor_sync(0xffffffffu, lsum, 2);
        if (q == 0) l_reg += lsum;

        // Prefetch next adj tile (hidden behind mma phase)
        const int jn = (ch < 63) ? (ch + 1) * 128 : 0;
        #pragma unroll
        for (int i = 0; i < 8; i++)
            adjv[i] = *(const int4*)&adj_row[jn + i * 16];

        __syncthreads();   // P_s / h_s ready

        // MMA phase: D[64x128] += P[64x128] @ h[128x128], tf32
        #pragma unroll
        for (int k0 = 0; k0 < 128; k0 += 8) {
            unsigned Af[2][4];
            #pragma unroll
            for (int mt = 0; mt < 2; mt++) {
                const float* pr = &P_s[(mb + mt * 16 + gID) * PS + k0];
                Af[mt][0] = __float_as_uint(pr[tig]);
                Af[mt][1] = __float_as_uint(pr[8 * PS + tig]);
                Af[mt][2] = __float_as_uint(pr[tig + 4]);
                Af[mt][3] = __float_as_uint(pr[8 * PS + tig + 4]);
            }
            unsigned Bf[4][2];
            #pragma unroll
            for (int nt = 0; nt < 4; nt++) {
                int nc = nb + nt * 8 + gID;
                Bf[nt][0] = __float_as_uint(h_s[(k0 + tig) * HS + nc]);
                Bf[nt][1] = __float_as_uint(h_s[(k0 + tig + 4) * HS + nc]);
            }
            #pragma unroll
            for (int mt = 0; mt < 2; mt++)
                #pragma unroll
                for (int nt = 0; nt < 4; nt++)
                    mma_tf32(acc[mt][nt], Af[mt], Bf[nt]);
        }
    }

    if (q == 0) l_s[row] = l_reg;
    __syncthreads();

    // Epilogue: normalize and store
    #pragma unroll
    for (int mt = 0; mt < 2; mt++) {
        const int ra = mb + mt * 16 + gID;
        const float inva = 1.f / l_s[ra];
        const float invb = 1.f / l_s[ra + 8];
        #pragma unroll
        for (int nt = 0; nt < 4; nt++) {
            const int c = nb + nt * 8 + 2 * tig;
            float2 v0, v1;
            v0.x = acc[mt][nt][0] * inva; v0.y = acc[mt][nt][1] * inva;
            v1.x = acc[mt][nt][2] * invb; v1.y = acc[mt][nt][3] * invb;
            *(float2*)&out[(r0 + ra) * F_OUT + c]     = v0;
            *(float2*)&out[(r0 + ra + 8) * F_OUT + c] = v1;
        }
    }
}

// ---------------------------------------------------------------------------
extern "C" void kernel_launch(void* const* d_in, const int* in_sizes, int n_in,
                              void* d_out, int out_size) {
    const float* x   = (const float*)d_in[0];
    const int*   adj = (const int*)  d_in[1];
    const float* W   = (const float*)d_in[2];
    const float* a   = (const float*)d_in[3];
    float* out = (float*)d_out;

    const int A_SMEM = (F_IN * F_OUT + 32 * 260) * 4;          // 164,352 B
    const int B_SMEM = (64 * 132 + 128 * 136 + 64) * 4;        // 103,680 B
    cudaFuncSetAttribute(prep_kernel, cudaFuncAttributeMaxDynamicSharedMemorySize, A_SMEM);
    cudaFuncSetAttribute(attn_kernel, cudaFuncAttributeMaxDynamicSharedMemorySize, B_SMEM);

    prep_kernel<<<128, 256, A_SMEM>>>(x, W, a);
    attn_kernel<<<128, 256, B_SMEM>>>(adj, out);
}

// round 3
// speedup vs baseline: 1.5290x; 1.5290x over previous
#include <cuda_runtime.h>
#include <cstdint>

#define N_NODES 8192
#define F_IN    256
#define F_OUT   128
#define NCHUNK  32     // 4096 j per CTA / 128 per chunk

// Scratch (device globals: no allocation allowed in kernel_launch)
__device__ float g_h[N_NODES * F_OUT];          // h = x@W, tf32-rounded, row-major
__device__ float g_src[N_NODES];
__device__ float g_dst[N_NODES];
__device__ float g_partD[256 * 64 * F_OUT];     // [cta][m][f] partial P@h
__device__ float g_partL[256 * 64];             // [cta][m] partial row sums

__device__ __forceinline__ float to_tf32(float v) {
    unsigned r;
    asm("cvt.rna.tf32.f32 %0, %1;" : "=r"(r) : "f"(v));
    return __uint_as_float(r);
}

__device__ __forceinline__ void mma_tf32(float* d, const unsigned* a, const unsigned* b) {
    asm volatile(
        "mma.sync.aligned.m16n8k8.row.col.f32.tf32.tf32.f32 "
        "{%0,%1,%2,%3}, {%4,%5,%6,%7}, {%8,%9}, {%0,%1,%2,%3};\n"
        : "+f"(d[0]), "+f"(d[1]), "+f"(d[2]), "+f"(d[3])
        : "r"(a[0]), "r"(a[1]), "r"(a[2]), "r"(a[3]), "r"(b[0]), "r"(b[1]));
}

// ---------------------------------------------------------------------------
// Kernel 1: h = x@W (fp32 exact), src = h@a1, dst = h@a2, store h tf32-rounded
// grid 128, block 256, 64 rows/block
// ---------------------------------------------------------------------------
__global__ void __launch_bounds__(256, 1)
prep_kernel(const float* __restrict__ x, const float* __restrict__ W,
            const float* __restrict__ a) {
    extern __shared__ float sm[];
    float* W_s = sm;                       // [256][128]
    float* x_s = sm + F_IN * F_OUT;        // [32][260] padded
    const int XS = 260;

    const int t  = threadIdx.x;
    const int tx = t & 15, ty = t >> 4;

    for (int i = t; i < F_IN * F_OUT / 4; i += 256)
        ((float4*)W_s)[i] = ((const float4*)W)[i];

    float a1v[8], a2v[8];
    #pragma unroll
    for (int e = 0; e < 4; e++) {
        a1v[e]     = a[4 * tx + e];
        a1v[4 + e] = a[64 + 4 * tx + e];
        a2v[e]     = a[F_OUT + 4 * tx + e];
        a2v[4 + e] = a[F_OUT + 64 + 4 * tx + e];
    }

    const int r0 = blockIdx.x * 64;
    for (int iter = 0; iter < 2; iter++) {
        __syncthreads();
        const int rbase = r0 + iter * 32;
        for (int i = t; i < 32 * 64; i += 256) {
            int r = i >> 6, c4 = i & 63;
            float4 v = *(const float4*)&x[(rbase + r) * F_IN + c4 * 4];
            *(float4*)&x_s[r * XS + c4 * 4] = v;
        }
        __syncthreads();

        float acc0[8], acc1[8];
        #pragma unroll
        for (int e = 0; e < 8; e++) { acc0[e] = 0.f; acc1[e] = 0.f; }

        #pragma unroll 8
        for (int k = 0; k < F_IN; k++) {
            float xa = x_s[ty * XS + k];
            float xb = x_s[(ty + 16) * XS + k];
            float4 w0 = *(const float4*)&W_s[k * F_OUT + 4 * tx];
            float4 w1 = *(const float4*)&W_s[k * F_OUT + 64 + 4 * tx];
            float wv[8] = {w0.x, w0.y, w0.z, w0.w, w1.x, w1.y, w1.z, w1.w};
            #pragma unroll
            for (int e = 0; e < 8; e++) {
                acc0[e] += xa * wv[e];
                acc1[e] += xb * wv[e];
            }
        }

        float sa = 0.f, da = 0.f, sb = 0.f, db = 0.f;
        #pragma unroll
        for (int e = 0; e < 8; e++) {
            sa += acc0[e] * a1v[e];  da += acc0[e] * a2v[e];
            sb += acc1[e] * a1v[e];  db += acc1[e] * a2v[e];
        }
        #pragma unroll
        for (int o = 8; o; o >>= 1) {
            sa += __shfl_down_sync(0xffffffffu, sa, o, 16);
            da += __shfl_down_sync(0xffffffffu, da, o, 16);
            sb += __shfl_down_sync(0xffffffffu, sb, o, 16);
            db += __shfl_down_sync(0xffffffffu, db, o, 16);
        }
        const int ra = rbase + ty, rb = rbase + ty + 16;
        if (tx == 0) {
            g_src[ra] = sa; g_dst[ra] = da;
            g_src[rb] = sb; g_dst[rb] = db;
        }

        float4 oa0, oa1, ob0, ob1;
        oa0.x = to_tf32(acc0[0]); oa0.y = to_tf32(acc0[1]); oa0.z = to_tf32(acc0[2]); oa0.w = to_tf32(acc0[3]);
        oa1.x = to_tf32(acc0[4]); oa1.y = to_tf32(acc0[5]); oa1.z = to_tf32(acc0[6]); oa1.w = to_tf32(acc0[7]);
        ob0.x = to_tf32(acc1[0]); ob0.y = to_tf32(acc1[1]); ob0.z = to_tf32(acc1[2]); ob0.w = to_tf32(acc1[3]);
        ob1.x = to_tf32(acc1[4]); ob1.y = to_tf32(acc1[5]); ob1.z = to_tf32(acc1[6]); ob1.w = to_tf32(acc1[7]);
        *(float4*)&g_h[ra * F_OUT + 4 * tx]      = oa0;
        *(float4*)&g_h[ra * F_OUT + 64 + 4 * tx] = oa1;
        *(float4*)&g_h[rb * F_OUT + 4 * tx]      = ob0;
        *(float4*)&g_h[rb * F_OUT + 64 + 4 * tx] = ob1;
    }
}

// ---------------------------------------------------------------------------
// Kernel 2: fused masked-softmax attention (tf32 mma.sync).
// grid 256: rb = bid>>1 (64 rows), jh = bid&1 (4096 j). 2 CTAs/SM for overlap.
// Writes unnormalized partials D and row-sums L; combine kernel finishes.
// ---------------------------------------------------------------------------
__global__ void __launch_bounds__(256, 2)
attn_kernel(const int* __restrict__ adj) {
    extern __shared__ float sm[];
    const int PS = 132, HS = 136;
    float* P_s = sm;                        // [64][132]
    float* h_s = sm + 64 * PS;              // [128][136]
    float* l_s = h_s + 128 * HS;            // [64]

    const int t    = threadIdx.x;
    const int rb   = blockIdx.x >> 1, jh = blockIdx.x & 1;
    const int r0   = rb * 64;
    const int jbase = jh * 4096;
    const int row  = t >> 2, q = t & 3;
    const int lane = t & 31, gID = lane >> 2, tig = lane & 3;
    const int w    = t >> 5;
    const int mb   = (w & 1) * 32, nb = (w >> 1) * 32;

    const float srcv = g_src[r0 + row];
    float l_reg = 0.f;

    float acc[2][4][4];
    #pragma unroll
    for (int mt = 0; mt < 2; mt++)
        #pragma unroll
        for (int nt = 0; nt < 4; nt++)
            #pragma unroll
            for (int c = 0; c < 4; c++) acc[mt][nt][c] = 0.f;

    const int* adj_row = adj + (size_t)(r0 + row) * N_NODES + jbase + q * 4;
    int4 adjv[8];
    #pragma unroll
    for (int i = 0; i < 8; i++)
        adjv[i] = *(const int4*)&adj_row[i * 16];

    for (int ch = 0; ch < NCHUNK; ch++) {
        const int j0 = ch * 128;            // within this CTA's 4096-j half
        __syncthreads();                    // previous mma done with P_s / h_s

        // Stage h tile [128 x 128]
        #pragma unroll 4
        for (int u = 0; u < 16; u++) {
            int idx = t + u * 256;
            int jr = idx >> 5, c4 = idx & 31;
            float4 v = *(const float4*)&g_h[(size_t)(jbase + j0 + jr) * F_OUT + c4 * 4];
            *(float4*)&h_s[jr * HS + c4 * 4] = v;
        }

        // Score phase: 32 cols per thread at {4q + 16i + e}
        float lsum = 0.f;
        #pragma unroll
        for (int i = 0; i < 8; i++) {
            const int cb = q * 4 + i * 16;
            int4 av = adjv[i];
            float4 dv = *(const float4*)&g_dst[jbase + j0 + cb];
            float4 pv;
            float s;
            s = srcv + dv.x; s = fmaxf(s, 0.2f * s); s = fminf(s, 80.f);
            pv.x = (av.x > 0) ? to_tf32(__expf(s)) : 0.f;
            s = srcv + dv.y; s = fmaxf(s, 0.2f * s); s = fminf(s, 80.f);
            pv.y = (av.y > 0) ? to_tf32(__expf(s)) : 0.f;
            s = srcv + dv.z; s = fmaxf(s, 0.2f * s); s = fminf(s, 80.f);
            pv.z = (av.z > 0) ? to_tf32(__expf(s)) : 0.f;
            s = srcv + dv.w; s = fmaxf(s, 0.2f * s); s = fminf(s, 80.f);
            pv.w = (av.w > 0) ? to_tf32(__expf(s)) : 0.f;
            lsum += (pv.x + pv.y) + (pv.z + pv.w);
            *(float4*)&P_s[row * PS + cb] = pv;
        }
        lsum += __shfl_xor_sync(0xffffffffu, lsum, 1);
        lsum += __shfl_xor_sync(0xffffffffu, lsum, 2);
        if (q == 0) l_reg += lsum;

        // Prefetch next adj tile (hidden behind mma phase)
        const int jn = (ch < NCHUNK - 1) ? (ch + 1) * 128 : 0;
        #pragma unroll
        for (int i = 0; i < 8; i++)
            adjv[i] = *(const int4*)&adj_row[jn + i * 16];

        __syncthreads();                    // P_s / h_s ready

        // MMA phase: D[64x128] += P[64x128] @ h[128x128], tf32
        #pragma unroll
        for (int k0 = 0; k0 < 128; k0 += 8) {
            unsigned Af[2][4];
            #pragma unroll
            for (int mt = 0; mt < 2; mt++) {
                const float* pr = &P_s[(mb + mt * 16 + gID) * PS + k0];
                Af[mt][0] = __float_as_uint(pr[tig]);
                Af[mt][1] = __float_as_uint(pr[8 * PS + tig]);
                Af[mt][2] = __float_as_uint(pr[tig + 4]);
                Af[mt][3] = __float_as_uint(pr[8 * PS + tig + 4]);
            }
            unsigned Bf[4][2];
            #pragma unroll
            for (int nt = 0; nt < 4; nt++) {
                int nc = nb + nt * 8 + gID;
                Bf[nt][0] = __float_as_uint(h_s[(k0 + tig) * HS + nc]);
                Bf[nt][1] = __float_as_uint(h_s[(k0 + tig + 4) * HS + nc]);
            }
            #pragma unroll
            for (int mt = 0; mt < 2; mt++)
                #pragma unroll
                for (int nt = 0; nt < 4; nt++)
                    mma_tf32(acc[mt][nt], Af[mt], Bf[nt]);
        }
    }

    if (q == 0) l_s[row] = l_reg;
    __syncthreads();

    // Epilogue: store unnormalized partials (combine kernel normalizes)
    const size_t dbase = (size_t)blockIdx.x * 64 * F_OUT;
    #pragma unroll
    for (int mt = 0; mt < 2; mt++) {
        const int ra = mb + mt * 16 + gID;
        #pragma unroll
        for (int nt = 0; nt < 4; nt++) {
            const int c = nb + nt * 8 + 2 * tig;
            float2 v0, v1;
            v0.x = acc[mt][nt][0]; v0.y = acc[mt][nt][1];
            v1.x = acc[mt][nt][2]; v1.y = acc[mt][nt][3];
            *(float2*)&g_partD[dbase + (size_t)ra * F_OUT + c]       = v0;
            *(float2*)&g_partD[dbase + (size_t)(ra + 8) * F_OUT + c] = v1;
        }
    }
    if (t < 64) g_partL[blockIdx.x * 64 + t] = l_s[t];
}

// ---------------------------------------------------------------------------
// Kernel 3: combine j-halves: out = (D0 + D1) / (l0 + l1)
// ---------------------------------------------------------------------------
__global__ void __launch_bounds__(512, 4)
combine_kernel(float* __restrict__ out) {
    const int idx  = blockIdx.x * 512 + threadIdx.x;  // 262144 float4 total
    const int rowc = idx >> 5;                        // 0..8191
    const int c4   = idx & 31;
    const int rbk  = rowc >> 6, m = rowc & 63;
    const size_t b0 = (size_t)(2 * rbk) * 64 * F_OUT + (size_t)m * F_OUT + c4 * 4;
    const float4 d0 = *(const float4*)&g_partD[b0];
    const float4 d1 = *(const float4*)&g_partD[b0 + 64 * F_OUT];
    const float inv = 1.f / (g_partL[(2 * rbk) * 64 + m] + g_partL[(2 * rbk + 1) * 64 + m]);
    float4 o;
    o.x = (d0.x + d1.x) * inv; o.y = (d0.y + d1.y) * inv;
    o.z = (d0.z + d1.z) * inv; o.w = (d0.w + d1.w) * inv;
    *(float4*)&out[(size_t)rowc * F_OUT + c4 * 4] = o;
}

// ---------------------------------------------------------------------------
extern "C" void kernel_launch(void* const* d_in, const int* in_sizes, int n_in,
                              void* d_out, int out_size) {
    const float* x   = (const float*)d_in[0];
    const int*   adj = (const int*)  d_in[1];
    const float* W   = (const float*)d_in[2];
    const float* a   = (const float*)d_in[3];
    float* out = (float*)d_out;

    const int A_SMEM = (F_IN * F_OUT + 32 * 260) * 4;          // 164,352 B
    const int B_SMEM = (64 * 132 + 128 * 136 + 64) * 4;        // 103,680 B
    cudaFuncSetAttribute(prep_kernel, cudaFuncAttributeMaxDynamicSharedMemorySize, A_SMEM);
    cudaFuncSetAttribute(attn_kernel, cudaFuncAttributeMaxDynamicSharedMemorySize, B_SMEM);

    prep_kernel<<<128, 256, A_SMEM>>>(x, W, a);
    attn_kernel<<<256, 256, B_SMEM>>>(adj);
    combine_kernel<<<512, 512>>>(out);
}

// round 4
// speedup vs baseline: 1.6002x; 1.0465x over previous
#include <cuda_runtime.h>
#include <cstdint>

#define N_NODES 8192
#define F_IN    256
#define F_OUT   128
#define KC      32      // j per chunk in attn
#define NCHUNK  64      // 2048 j per CTA / KC

// Scratch (device globals: no allocation allowed in kernel_launch)
__device__ float g_h[N_NODES * F_OUT];          // h = x@W, tf32-rounded, row-major
__device__ float g_src[N_NODES];
__device__ float g_dst[N_NODES];
__device__ float g_partD[512 * 64 * F_OUT];     // [cta][m][f] partial P@h
__device__ float g_partL[512 * 64];             // [cta][m] partial row sums

__device__ __forceinline__ float to_tf32(float v) {
    unsigned r;
    asm("cvt.rna.tf32.f32 %0, %1;" : "=r"(r) : "f"(v));
    return __uint_as_float(r);
}

__device__ __forceinline__ void mma_tf32(float* d, const unsigned* a, const unsigned* b) {
    asm volatile(
        "mma.sync.aligned.m16n8k8.row.col.f32.tf32.tf32.f32 "
        "{%0,%1,%2,%3}, {%4,%5,%6,%7}, {%8,%9}, {%0,%1,%2,%3};\n"
        : "+f"(d[0]), "+f"(d[1]), "+f"(d[2]), "+f"(d[3])
        : "r"(a[0]), "r"(a[1]), "r"(a[2]), "r"(a[3]), "r"(b[0]), "r"(b[1]));
}

// ---------------------------------------------------------------------------
// Kernel 1: h = x@W (fp32 exact), src/dst, h stored tf32-rounded.
// grid 256 (32 rows each), block 256, W staged in two 64KB k-halves -> 2 CTA/SM
// ---------------------------------------------------------------------------
__global__ void __launch_bounds__(256, 2)
prep_kernel(const float* __restrict__ x, const float* __restrict__ W,
            const float* __restrict__ a) {
    extern __shared__ float sm[];
    float* W_s = sm;                       // [128 k][128 f]
    float* x_s = sm + 128 * F_OUT;         // [32 rows][132]
    const int XS = 132;

    const int t  = threadIdx.x;
    const int tx = t & 15, ty = t >> 4;
    const int rbase = blockIdx.x * 32;

    float a1v[8], a2v[8];
    #pragma unroll
    for (int e = 0; e < 4; e++) {
        a1v[e]     = a[4 * tx + e];
        a1v[4 + e] = a[64 + 4 * tx + e];
        a2v[e]     = a[F_OUT + 4 * tx + e];
        a2v[4 + e] = a[F_OUT + 64 + 4 * tx + e];
    }

    float acc0[8], acc1[8];
    #pragma unroll
    for (int e = 0; e < 8; e++) { acc0[e] = 0.f; acc1[e] = 0.f; }

    for (int kh = 0; kh < 2; kh++) {
        __syncthreads();
        // Stage W half [128][128]
        for (int i = t; i < 128 * 32; i += 256) {
            int k = i >> 5, c4 = i & 31;
            *(float4*)&W_s[k * F_OUT + c4 * 4] =
                *(const float4*)&W[(kh * 128 + k) * F_OUT + c4 * 4];
        }
        // Stage x slice [32][128]
        for (int i = t; i < 32 * 32; i += 256) {
            int r = i >> 5, c4 = i & 31;
            *(float4*)&x_s[r * XS + c4 * 4] =
                *(const float4*)&x[(rbase + r) * F_IN + kh * 128 + c4 * 4];
        }
        __syncthreads();

        #pragma unroll 8
        for (int k = 0; k < 128; k++) {
            float xa = x_s[ty * XS + k];
            float xb = x_s[(ty + 16) * XS + k];
            float4 w0 = *(const float4*)&W_s[k * F_OUT + 4 * tx];
            float4 w1 = *(const float4*)&W_s[k * F_OUT + 64 + 4 * tx];
            float wv[8] = {w0.x, w0.y, w0.z, w0.w, w1.x, w1.y, w1.z, w1.w};
            #pragma unroll
            for (int e = 0; e < 8; e++) {
                acc0[e] += xa * wv[e];
                acc1[e] += xb * wv[e];
            }
        }
    }

    float sa = 0.f, da = 0.f, sb = 0.f, db = 0.f;
    #pragma unroll
    for (int e = 0; e < 8; e++) {
        sa += acc0[e] * a1v[e];  da += acc0[e] * a2v[e];
        sb += acc1[e] * a1v[e];  db += acc1[e] * a2v[e];
    }
    #pragma unroll
    for (int o = 8; o; o >>= 1) {
        sa += __shfl_down_sync(0xffffffffu, sa, o, 16);
        da += __shfl_down_sync(0xffffffffu, da, o, 16);
        sb += __shfl_down_sync(0xffffffffu, sb, o, 16);
        db += __shfl_down_sync(0xffffffffu, db, o, 16);
    }
    const int ra = rbase + ty, rb = rbase + ty + 16;
    if (tx == 0) {
        g_src[ra] = sa; g_dst[ra] = da;
        g_src[rb] = sb; g_dst[rb] = db;
    }

    float4 oa0, oa1, ob0, ob1;
    oa0.x = to_tf32(acc0[0]); oa0.y = to_tf32(acc0[1]); oa0.z = to_tf32(acc0[2]); oa0.w = to_tf32(acc0[3]);
    oa1.x = to_tf32(acc0[4]); oa1.y = to_tf32(acc0[5]); oa1.z = to_tf32(acc0[6]); oa1.w = to_tf32(acc0[7]);
    ob0.x = to_tf32(acc1[0]); ob0.y = to_tf32(acc1[1]); ob0.z = to_tf32(acc1[2]); ob0.w = to_tf32(acc1[3]);
    ob1.x = to_tf32(acc1[4]); ob1.y = to_tf32(acc1[5]); ob1.z = to_tf32(acc1[6]); ob1.w = to_tf32(acc1[7]);
    *(float4*)&g_h[ra * F_OUT + 4 * tx]      = oa0;
    *(float4*)&g_h[ra * F_OUT + 64 + 4 * tx] = oa1;
    *(float4*)&g_h[rb * F_OUT + 4 * tx]      = ob0;
    *(float4*)&g_h[rb * F_OUT + 64 + 4 * tx] = ob1;
}

// ---------------------------------------------------------------------------
// Kernel 2: fused masked-softmax attention (tf32 mma.sync), 4 CTAs/SM.
// grid 512: rb = bid>>2 (64 rows), jq = bid&3 (2048 j). block 128 (4 warps).
// Warp tile 32x64. Chunks of KC=32 j. Unnormalized partials to g_partD/L.
// ---------------------------------------------------------------------------
__global__ void __launch_bounds__(128, 4)
attn_kernel(const int* __restrict__ adj) {
    extern __shared__ float sm[];
    const int PS = 36, HS = 132;
    float* P_s = sm;                        // [64][36]
    float* h_s = sm + 64 * PS;              // [32][132]
    float* l_s = h_s + 32 * HS;             // [64]

    const int t     = threadIdx.x;
    const int rb    = blockIdx.x >> 2, jq = blockIdx.x & 3;
    const int r0    = rb * 64;
    const int jbase = jq * 2048;
    const int row   = t >> 1, q = t & 1;    // score: 2 threads/row, 16 cols each
    const int lane  = t & 31, gID = lane >> 2, tig = lane & 3;
    const int w     = t >> 5;
    const int mb    = (w & 1) * 32, nb = (w >> 1) * 64;

    const float srcv = g_src[r0 + row];
    float l_reg = 0.f;

    float acc[2][8][4];
    #pragma unroll
    for (int mt = 0; mt < 2; mt++)
        #pragma unroll
        for (int nt = 0; nt < 8; nt++)
            #pragma unroll
            for (int c = 0; c < 4; c++) acc[mt][nt][c] = 0.f;

    // thread covers cols c = 4q + 8i + {0..3}, i = 0..3, within each 32-chunk
    const int* adj_row = adj + (size_t)(r0 + row) * N_NODES + jbase + q * 4;
    int4 adjv[4];
    #pragma unroll
    for (int i = 0; i < 4; i++)
        adjv[i] = *(const int4*)&adj_row[i * 8];

    for (int ch = 0; ch < NCHUNK; ch++) {
        const int j0 = ch * KC;
        __syncthreads();                    // previous mma done with P_s / h_s

        // Stage h tile [32 j][128 f]
        #pragma unroll
        for (int u = 0; u < 8; u++) {
            int idx = t + u * 128;
            int jr = idx >> 5, c4 = idx & 31;
            float4 v = *(const float4*)&g_h[(size_t)(jbase + j0 + jr) * F_OUT + c4 * 4];
            *(float4*)&h_s[jr * HS + c4 * 4] = v;
        }

        // Score phase: 16 cols per thread
        float lsum = 0.f;
        #pragma unroll
        for (int i = 0; i < 4; i++) {
            const int cb = q * 4 + i * 8;
            int4 av = adjv[i];
            float4 dv = *(const float4*)&g_dst[jbase + j0 + cb];
            float4 pv;
            float s;
            s = srcv + dv.x; s = fmaxf(s, 0.2f * s);
            pv.x = (av.x > 0) ? to_tf32(__expf(s)) : 0.f;
            s = srcv + dv.y; s = fmaxf(s, 0.2f * s);
            pv.y = (av.y > 0) ? to_tf32(__expf(s)) : 0.f;
            s = srcv + dv.z; s = fmaxf(s, 0.2f * s);
            pv.z = (av.z > 0) ? to_tf32(__expf(s)) : 0.f;
            s = srcv + dv.w; s = fmaxf(s, 0.2f * s);
            pv.w = (av.w > 0) ? to_tf32(__expf(s)) : 0.f;
            lsum += (pv.x + pv.y) + (pv.z + pv.w);
            *(float4*)&P_s[row * PS + cb] = pv;
        }
        lsum += __shfl_xor_sync(0xffffffffu, lsum, 1);
        if (q == 0) l_reg += lsum;

        // Prefetch next chunk's adj (lands during mma phase)
        const int jn = (ch < NCHUNK - 1) ? (ch + 1) * KC : 0;
        #pragma unroll
        for (int i = 0; i < 4; i++)
            adjv[i] = *(const int4*)&adj_row[jn + i * 8];

        __syncthreads();                    // P_s / h_s ready

        // MMA phase: D[64x128] += P[64x32] @ h[32x128]
        #pragma unroll
        for (int k0 = 0; k0 < KC; k0 += 8) {
            unsigned Af[2][4];
            #pragma unroll
            for (int mt = 0; mt < 2; mt++) {
                const float* pr = &P_s[(mb + mt * 16 + gID) * PS + k0];
                Af[mt][0] = __float_as_uint(pr[tig]);
                Af[mt][1] = __float_as_uint(pr[8 * PS + tig]);
                Af[mt][2] = __float_as_uint(pr[tig + 4]);
                Af[mt][3] = __float_as_uint(pr[8 * PS + tig + 4]);
            }
            #pragma unroll
            for (int nt = 0; nt < 8; nt++) {
                unsigned Bf[2];
                const int nc = nb + nt * 8 + gID;
                Bf[0] = __float_as_uint(h_s[(k0 + tig) * HS + nc]);
                Bf[1] = __float_as_uint(h_s[(k0 + tig + 4) * HS + nc]);
                mma_tf32(acc[0][nt], Af[0], Bf);
                mma_tf32(acc[1][nt], Af[1], Bf);
            }
        }
    }

    if (q == 0) l_s[row] = l_reg;
    __syncthreads();

    // Epilogue: store unnormalized partials
    const size_t dbase = (size_t)blockIdx.x * 64 * F_OUT;
    #pragma unroll
    for (int mt = 0; mt < 2; mt++) {
        const int ra = mb + mt * 16 + gID;
        #pragma unroll
        for (int nt = 0; nt < 8; nt++) {
            const int c = nb + nt * 8 + 2 * tig;
            float2 v0, v1;
            v0.x = acc[mt][nt][0]; v0.y = acc[mt][nt][1];
            v1.x = acc[mt][nt][2]; v1.y = acc[mt][nt][3];
            *(float2*)&g_partD[dbase + (size_t)ra * F_OUT + c]       = v0;
            *(float2*)&g_partD[dbase + (size_t)(ra + 8) * F_OUT + c] = v1;
        }
    }
    if (t < 64) g_partL[blockIdx.x * 64 + t] = l_s[t];
}

// ---------------------------------------------------------------------------
// Kernel 3: combine 4 j-quarters: out = sum(D_p) / sum(l_p)
// ---------------------------------------------------------------------------
__global__ void __launch_bounds__(512, 4)
combine_kernel(float* __restrict__ out) {
    const int idx  = blockIdx.x * 512 + threadIdx.x;  // 262144 float4 total
    const int rowc = idx >> 5;                        // 0..8191
    const int c4   = idx & 31;
    const int rbk  = rowc >> 6, m = rowc & 63;
    const size_t b0 = (size_t)(4 * rbk) * 64 * F_OUT + (size_t)m * F_OUT + c4 * 4;
    float4 d0 = *(const float4*)&g_partD[b0];
    const float4 d1 = *(const float4*)&g_partD[b0 + 1 * 64 * F_OUT];
    const float4 d2 = *(const float4*)&g_partD[b0 + 2 * 64 * F_OUT];
    const float4 d3 = *(const float4*)&g_partD[b0 + 3 * 64 * F_OUT];
    const float lsum = g_partL[(4 * rbk + 0) * 64 + m] + g_partL[(4 * rbk + 1) * 64 + m]
                     + g_partL[(4 * rbk + 2) * 64 + m] + g_partL[(4 * rbk + 3) * 64 + m];
    const float inv = 1.f / lsum;
    float4 o;
    o.x = ((d0.x + d1.x) + (d2.x + d3.x)) * inv;
    o.y = ((d0.y + d1.y) + (d2.y + d3.y)) * inv;
    o.z = ((d0.z + d1.z) + (d2.z + d3.z)) * inv;
    o.w = ((d0.w + d1.w) + (d2.w + d3.w)) * inv;
    *(float4*)&out[(size_t)rowc * F_OUT + c4 * 4] = o;
}

// ---------------------------------------------------------------------------
extern "C" void kernel_launch(void* const* d_in, const int* in_sizes, int n_in,
                              void* d_out, int out_size) {
    const float* x   = (const float*)d_in[0];
    const int*   adj = (const int*)  d_in[1];
    const float* W   = (const float*)d_in[2];
    const float* a   = (const float*)d_in[3];
    float* out = (float*)d_out;

    const int A_SMEM = (128 * F_OUT + 32 * 132) * 4;           // 82,432 B
    const int B_SMEM = (64 * 36 + 32 * 132 + 64) * 4;          // 26,368 B
    cudaFuncSetAttribute(prep_kernel, cudaFuncAttributeMaxDynamicSharedMemorySize, A_SMEM);
    cudaFuncSetAttribute(attn_kernel, cudaFuncAttributeMaxDynamicSharedMemorySize, B_SMEM);

    prep_kernel<<<256, 256, A_SMEM>>>(x, W, a);
    attn_kernel<<<512, 128, B_SMEM>>>(adj);
    combine_kernel<<<512, 512>>>(out);
}

// round 5
// speedup vs baseline: 1.6149x; 1.0092x over previous
#include <cuda_runtime.h>
#include <cstdint>

#define N_NODES 8192
#define F_IN    256
#define F_OUT   128
#define KC      32      // j per chunk in attn
#define NCHUNK  64      // 2048 j per CTA / KC
#define LOG2E   1.4426950408889634f

// Scratch (device globals: no allocation allowed in kernel_launch)
__device__ float g_h[N_NODES * F_OUT];          // h = x@W, tf32-rounded, row-major
__device__ float g_src[N_NODES];                // src * log2e
__device__ float g_dst[N_NODES];                // dst * log2e
__device__ float g_partD[512 * 64 * F_OUT];     // [cta][m][f] partial P@h
__device__ float g_partL[512 * 64];             // [cta][m] partial row sums

__device__ __forceinline__ float to_tf32(float v) {
    unsigned r;
    asm("cvt.rna.tf32.f32 %0, %1;" : "=r"(r) : "f"(v));
    return __uint_as_float(r);
}
__device__ __forceinline__ float ex2(float v) {
    float r;
    asm("ex2.approx.f32 %0, %1;" : "=f"(r) : "f"(v));
    return r;
}

__device__ __forceinline__ void mma_tf32(float* d, const unsigned* a, const unsigned* b) {
    asm volatile(
        "mma.sync.aligned.m16n8k8.row.col.f32.tf32.tf32.f32 "
        "{%0,%1,%2,%3}, {%4,%5,%6,%7}, {%8,%9}, {%0,%1,%2,%3};\n"
        : "+f"(d[0]), "+f"(d[1]), "+f"(d[2]), "+f"(d[3])
        : "r"(a[0]), "r"(a[1]), "r"(a[2]), "r"(a[3]), "r"(b[0]), "r"(b[1]));
}

// ---------------------------------------------------------------------------
// Kernel 1: h = x@W (fp32 exact), src/dst (scaled by log2e), h tf32-rounded.
// grid 128 (64 rows), block 256, 4 rows/thread, W staged in two k-halves.
// ---------------------------------------------------------------------------
__global__ void __launch_bounds__(256, 2)
prep_kernel(const float* __restrict__ x, const float* __restrict__ W,
            const float* __restrict__ a) {
    extern __shared__ float sm[];
    float* W_s = sm;                       // [128 k][128 f]
    float* x_s = sm + 128 * F_OUT;         // [64 rows][132]
    const int XS = 132;

    const int t  = threadIdx.x;
    const int tx = t & 15, ty = t >> 4;
    const int rbase = blockIdx.x * 64;

    float a1v[8], a2v[8];
    #pragma unroll
    for (int e = 0; e < 4; e++) {
        a1v[e]     = a[4 * tx + e];
        a1v[4 + e] = a[64 + 4 * tx + e];
        a2v[e]     = a[F_OUT + 4 * tx + e];
        a2v[4 + e] = a[F_OUT + 64 + 4 * tx + e];
    }

    float acc[4][8];
    #pragma unroll
    for (int u = 0; u < 4; u++)
        #pragma unroll
        for (int e = 0; e < 8; e++) acc[u][e] = 0.f;

    for (int kh = 0; kh < 2; kh++) {
        __syncthreads();
        // Stage W half [128][128]: 4096 float4
        for (int i = t; i < 4096; i += 256) {
            int k = i >> 5, c4 = i & 31;
            *(float4*)&W_s[k * F_OUT + c4 * 4] =
                *(const float4*)&W[(kh * 128 + k) * F_OUT + c4 * 4];
        }
        // Stage x slice [64][128]: 2048 float4
        for (int i = t; i < 2048; i += 256) {
            int r = i >> 5, c4 = i & 31;
            *(float4*)&x_s[r * XS + c4 * 4] =
                *(const float4*)&x[(rbase + r) * F_IN + kh * 128 + c4 * 4];
        }
        __syncthreads();

        #pragma unroll 4
        for (int k = 0; k < 128; k++) {
            float xv[4];
            #pragma unroll
            for (int u = 0; u < 4; u++) xv[u] = x_s[(ty + 16 * u) * XS + k];
            float4 w0 = *(const float4*)&W_s[k * F_OUT + 4 * tx];
            float4 w1 = *(const float4*)&W_s[k * F_OUT + 64 + 4 * tx];
            float wv[8] = {w0.x, w0.y, w0.z, w0.w, w1.x, w1.y, w1.z, w1.w};
            #pragma unroll
            for (int u = 0; u < 4; u++)
                #pragma unroll
                for (int e = 0; e < 8; e++)
                    acc[u][e] += xv[u] * wv[e];
        }
    }

    #pragma unroll
    for (int u = 0; u < 4; u++) {
        float sa = 0.f, da = 0.f;
        #pragma unroll
        for (int e = 0; e < 8; e++) {
            sa += acc[u][e] * a1v[e];
            da += acc[u][e] * a2v[e];
        }
        #pragma unroll
        for (int o = 8; o; o >>= 1) {
            sa += __shfl_down_sync(0xffffffffu, sa, o, 16);
            da += __shfl_down_sync(0xffffffffu, da, o, 16);
        }
        const int r = rbase + ty + 16 * u;
        if (tx == 0) {
            g_src[r] = sa * LOG2E;
            g_dst[r] = da * LOG2E;
        }
        float4 o0, o1;
        o0.x = to_tf32(acc[u][0]); o0.y = to_tf32(acc[u][1]);
        o0.z = to_tf32(acc[u][2]); o0.w = to_tf32(acc[u][3]);
        o1.x = to_tf32(acc[u][4]); o1.y = to_tf32(acc[u][5]);
        o1.z = to_tf32(acc[u][6]); o1.w = to_tf32(acc[u][7]);
        *(float4*)&g_h[(size_t)r * F_OUT + 4 * tx]      = o0;
        *(float4*)&g_h[(size_t)r * F_OUT + 64 + 4 * tx] = o1;
    }
}

// ---------------------------------------------------------------------------
// Kernel 2: fused masked-softmax attention, software-pipelined, 4 CTAs/SM.
// grid 512: rb = bid>>2 (64 rows), jq = bid&3 (2048 j). block 128 (4 warps).
// Double-buffered P/h; one barrier per chunk; score(c+1) overlaps MMA(c).
// ---------------------------------------------------------------------------
__global__ void __launch_bounds__(128, 4)
attn_kernel(const int* __restrict__ adj) {
    extern __shared__ float sm[];
    const int PS = 36, HS = 132;
    // layout: P0[64*36] P1[64*36] H0[32*132] H1[32*132] l_s[64]
    float* l_s = sm + 2 * 2304 + 2 * 4224;

    const int t     = threadIdx.x;
    const int rb    = blockIdx.x >> 2, jq = blockIdx.x & 3;
    const int r0    = rb * 64;
    const int jbase = jq * 2048;
    const int row   = t >> 1, q = t & 1;
    const int lane  = t & 31, gID = lane >> 2, tig = lane & 3;
    const int w     = t >> 5;
    const int mb    = (w & 1) * 32, nb = (w >> 1) * 64;

    const float srcv = g_src[r0 + row];
    float l_reg = 0.f;

    float acc[2][8][4];
    #pragma unroll
    for (int mt = 0; mt < 2; mt++)
        #pragma unroll
        for (int nt = 0; nt < 8; nt++)
            #pragma unroll
            for (int c = 0; c < 4; c++) acc[mt][nt][c] = 0.f;

    const int* adj_row = adj + (size_t)(r0 + row) * N_NODES + jbase + q * 4;

    int4 adjv[4];
    #pragma unroll
    for (int i = 0; i < 4; i++)
        adjv[i] = *(const int4*)&adj_row[i * 8];

    // ---------------- prologue: stage chunk 0 ----------------
    {
        float* H0 = sm + 2 * 2304;
        #pragma unroll
        for (int u = 0; u < 8; u++) {
            int idx = t + u * 128;
            int jr = idx >> 5, c4 = idx & 31;
            *(float4*)&H0[jr * HS + c4 * 4] =
                *(const float4*)&g_h[(size_t)(jbase + jr) * F_OUT + c4 * 4];
        }
        float* P0 = sm;
        float lsum = 0.f;
        #pragma unroll
        for (int i = 0; i < 4; i++) {
            const int cb = q * 4 + i * 8;
            int4 av = adjv[i];
            float4 dv = *(const float4*)&g_dst[jbase + cb];
            float4 pv;
            float s;
            s = srcv + dv.x; s = fmaxf(s, 0.2f * s);
            pv.x = (av.x > 0) ? ex2(s) : 0.f;
            s = srcv + dv.y; s = fmaxf(s, 0.2f * s);
            pv.y = (av.y > 0) ? ex2(s) : 0.f;
            s = srcv + dv.z; s = fmaxf(s, 0.2f * s);
            pv.z = (av.z > 0) ? ex2(s) : 0.f;
            s = srcv + dv.w; s = fmaxf(s, 0.2f * s);
            pv.w = (av.w > 0) ? ex2(s) : 0.f;
            lsum += (pv.x + pv.y) + (pv.z + pv.w);
            *(float4*)&P0[row * PS + cb] = pv;
        }
        lsum += __shfl_xor_sync(0xffffffffu, lsum, 1);
        if (q == 0) l_reg += lsum;
        // prefetch adj for chunk 1
        #pragma unroll
        for (int i = 0; i < 4; i++)
            adjv[i] = *(const int4*)&adj_row[KC + i * 8];
    }
    __syncthreads();

    // ---------------- main pipelined loop ----------------
    #pragma unroll 2
    for (int ch = 0; ch < NCHUNK; ch++) {
        const int buf = ch & 1;
        float* Pc = sm + buf * 2304;
        float* Hc = sm + 2 * 2304 + buf * 4224;
        float* Pn = sm + (buf ^ 1) * 2304;
        float* Hn = sm + 2 * 2304 + (buf ^ 1) * 4224;

        if (ch + 1 < NCHUNK) {
            const int j0n = (ch + 1) * KC;
            // stage h(ch+1)
            #pragma unroll
            for (int u = 0; u < 8; u++) {
                int idx = t + u * 128;
                int jr = idx >> 5, c4 = idx & 31;
                *(float4*)&Hn[jr * HS + c4 * 4] =
                    *(const float4*)&g_h[(size_t)(jbase + j0n + jr) * F_OUT + c4 * 4];
            }
            // scores(ch+1)
            float lsum = 0.f;
            #pragma unroll
            for (int i = 0; i < 4; i++) {
                const int cb = q * 4 + i * 8;
                int4 av = adjv[i];
                float4 dv = *(const float4*)&g_dst[jbase + j0n + cb];
                float4 pv;
                float s;
                s = srcv + dv.x; s = fmaxf(s, 0.2f * s);
                pv.x = (av.x > 0) ? ex2(s) : 0.f;
                s = srcv + dv.y; s = fmaxf(s, 0.2f * s);
                pv.y = (av.y > 0) ? ex2(s) : 0.f;
                s = srcv + dv.z; s = fmaxf(s, 0.2f * s);
                pv.z = (av.z > 0) ? ex2(s) : 0.f;
                s = srcv + dv.w; s = fmaxf(s, 0.2f * s);
                pv.w = (av.w > 0) ? ex2(s) : 0.f;
                lsum += (pv.x + pv.y) + (pv.z + pv.w);
                *(float4*)&Pn[row * PS + cb] = pv;
            }
            lsum += __shfl_xor_sync(0xffffffffu, lsum, 1);
            if (q == 0) l_reg += lsum;
            // prefetch adj for ch+2 (clamped; extra load harmless)
            const int j2 = (ch + 2 < NCHUNK) ? (ch + 2) * KC : 0;
            #pragma unroll
            for (int i = 0; i < 4; i++)
                adjv[i] = *(const int4*)&adj_row[j2 + i * 8];
        }

        // MMA(ch): D[64x128] += P[64x32] @ h[32x128]
        #pragma unroll
        for (int k0 = 0; k0 < KC; k0 += 8) {
            unsigned Af[2][4];
            #pragma unroll
            for (int mt = 0; mt < 2; mt++) {
                const float* pr = &Pc[(mb + mt * 16 + gID) * PS + k0];
                Af[mt][0] = __float_as_uint(pr[tig]);
                Af[mt][1] = __float_as_uint(pr[8 * PS + tig]);
                Af[mt][2] = __float_as_uint(pr[tig + 4]);
                Af[mt][3] = __float_as_uint(pr[8 * PS + tig + 4]);
            }
            #pragma unroll
            for (int nt = 0; nt < 8; nt++) {
                unsigned Bf[2];
                const int nc = nb + nt * 8 + gID;
                Bf[0] = __float_as_uint(Hc[(k0 + tig) * HS + nc]);
                Bf[1] = __float_as_uint(Hc[(k0 + tig + 4) * HS + nc]);
                mma_tf32(acc[0][nt], Af[0], Bf);
                mma_tf32(acc[1][nt], Af[1], Bf);
            }
        }
        __syncthreads();
    }

    if (q == 0) l_s[row] = l_reg;
    __syncthreads();

    // Epilogue: store unnormalized partials
    const size_t dbase = (size_t)blockIdx.x * 64 * F_OUT;
    #pragma unroll
    for (int mt = 0; mt < 2; mt++) {
        const int ra = mb + mt * 16 + gID;
        #pragma unroll
        for (int nt = 0; nt < 8; nt++) {
            const int c = nb + nt * 8 + 2 * tig;
            float2 v0, v1;
            v0.x = acc[mt][nt][0]; v0.y = acc[mt][nt][1];
            v1.x = acc[mt][nt][2]; v1.y = acc[mt][nt][3];
            *(float2*)&g_partD[dbase + (size_t)ra * F_OUT + c]       = v0;
            *(float2*)&g_partD[dbase + (size_t)(ra + 8) * F_OUT + c] = v1;
        }
    }
    if (t < 64) g_partL[blockIdx.x * 64 + t] = l_s[t];
}

// ---------------------------------------------------------------------------
// Kernel 3: combine 4 j-quarters: out = sum(D_p) / sum(l_p)
// ---------------------------------------------------------------------------
__global__ void __launch_bounds__(512, 4)
combine_kernel(float* __restrict__ out) {
    const int idx  = blockIdx.x * 512 + threadIdx.x;  // 262144 float4 total
    const int rowc = idx >> 5;                        // 0..8191
    const int c4   = idx & 31;
    const int rbk  = rowc >> 6, m = rowc & 63;
    const size_t b0 = (size_t)(4 * rbk) * 64 * F_OUT + (size_t)m * F_OUT + c4 * 4;
    const float4 d0 = *(const float4*)&g_partD[b0];
    const float4 d1 = *(const float4*)&g_partD[b0 + 1 * 64 * F_OUT];
    const float4 d2 = *(const float4*)&g_partD[b0 + 2 * 64 * F_OUT];
    const float4 d3 = *(const float4*)&g_partD[b0 + 3 * 64 * F_OUT];
    const float lsum = g_partL[(4 * rbk + 0) * 64 + m] + g_partL[(4 * rbk + 1) * 64 + m]
                     + g_partL[(4 * rbk + 2) * 64 + m] + g_partL[(4 * rbk + 3) * 64 + m];
    const float inv = 1.f / lsum;
    float4 o;
    o.x = ((d0.x + d1.x) + (d2.x + d3.x)) * inv;
    o.y = ((d0.y + d1.y) + (d2.y + d3.y)) * inv;
    o.z = ((d0.z + d1.z) + (d2.z + d3.z)) * inv;
    o.w = ((d0.w + d1.w) + (d2.w + d3.w)) * inv;
    *(float4*)&out[(size_t)rowc * F_OUT + c4 * 4] = o;
}

// ---------------------------------------------------------------------------
extern "C" void kernel_launch(void* const* d_in, const int* in_sizes, int n_in,
                              void* d_out, int out_size) {
    const float* x   = (const float*)d_in[0];
    const int*   adj = (const int*)  d_in[1];
    const float* W   = (const float*)d_in[2];
    const float* a   = (const float*)d_in[3];
    float* out = (float*)d_out;

    const int A_SMEM = (128 * F_OUT + 64 * 132) * 4;            // 99,328 B
    const int B_SMEM = (2 * 2304 + 2 * 4224 + 64) * 4;          // 52,480 B
    cudaFuncSetAttribute(prep_kernel, cudaFuncAttributeMaxDynamicSharedMemorySize, A_SMEM);
    cudaFuncSetAttribute(attn_kernel, cudaFuncAttributeMaxDynamicSharedMemorySize, B_SMEM);

    prep_kernel<<<128, 256, A_SMEM>>>(x, W, a);
    attn_kernel<<<512, 128, B_SMEM>>>(adj);
    combine_kernel<<<512, 512>>>(out);
}

// round 6
// speedup vs baseline: 1.6952x; 1.0497x over previous
#include <cuda_runtime.h>
#include <cstdint>

#define N_NODES 8192
#define F_IN    256
#define F_OUT   128
#define KC      32      // j per chunk in attn
#define NCHUNK  64      // 2048 j per CTA / KC
#define LOG2E   1.4426950408889634f

// Scratch (device globals: no allocation allowed in kernel_launch)
__device__ float g_h[N_NODES * F_OUT];          // h = x@W, tf32-rounded, row-major
__device__ float g_src[N_NODES];                // src * log2e
__device__ float g_dst[N_NODES];                // dst * log2e
__device__ float g_partD[512 * 64 * F_OUT];     // [cta][m][f] partial P@h
__device__ float g_partL[512 * 64];             // [cta][m] partial row sums

__device__ __forceinline__ float to_tf32(float v) {
    unsigned r;
    asm("cvt.rna.tf32.f32 %0, %1;" : "=r"(r) : "f"(v));
    return __uint_as_float(r);
}
__device__ __forceinline__ float ex2(float v) {
    float r;
    asm("ex2.approx.f32 %0, %1;" : "=f"(r) : "f"(v));
    return r;
}

__device__ __forceinline__ void mma_tf32(float* d, const unsigned* a, const unsigned* b) {
    asm volatile(
        "mma.sync.aligned.m16n8k8.row.col.f32.tf32.tf32.f32 "
        "{%0,%1,%2,%3}, {%4,%5,%6,%7}, {%8,%9}, {%0,%1,%2,%3};\n"
        : "+f"(d[0]), "+f"(d[1]), "+f"(d[2]), "+f"(d[3])
        : "r"(a[0]), "r"(a[1]), "r"(a[2]), "r"(a[3]), "r"(b[0]), "r"(b[1]));
}

// ---------------------------------------------------------------------------
// Kernel 1: h = x@W (fp32 exact), src/dst (scaled by log2e), h tf32-rounded.
// grid 128 (64 rows), block 256, 4 rows/thread, W staged in two k-halves.
// ---------------------------------------------------------------------------
__global__ void __launch_bounds__(256, 2)
prep_kernel(const float* __restrict__ x, const float* __restrict__ W,
            const float* __restrict__ a) {
    extern __shared__ float sm[];
    float* W_s = sm;                       // [128 k][128 f]
    float* x_s = sm + 128 * F_OUT;         // [64 rows][132]
    const int XS = 132;

    const int t  = threadIdx.x;
    const int tx = t & 15, ty = t >> 4;
    const int rbase = blockIdx.x * 64;

    float a1v[8], a2v[8];
    #pragma unroll
    for (int e = 0; e < 4; e++) {
        a1v[e]     = a[4 * tx + e];
        a1v[4 + e] = a[64 + 4 * tx + e];
        a2v[e]     = a[F_OUT + 4 * tx + e];
        a2v[4 + e] = a[F_OUT + 64 + 4 * tx + e];
    }

    float acc[4][8];
    #pragma unroll
    for (int u = 0; u < 4; u++)
        #pragma unroll
        for (int e = 0; e < 8; e++) acc[u][e] = 0.f;

    for (int kh = 0; kh < 2; kh++) {
        __syncthreads();
        for (int i = t; i < 4096; i += 256) {
            int k = i >> 5, c4 = i & 31;
            *(float4*)&W_s[k * F_OUT + c4 * 4] =
                *(const float4*)&W[(kh * 128 + k) * F_OUT + c4 * 4];
        }
        for (int i = t; i < 2048; i += 256) {
            int r = i >> 5, c4 = i & 31;
            *(float4*)&x_s[r * XS + c4 * 4] =
                *(const float4*)&x[(rbase + r) * F_IN + kh * 128 + c4 * 4];
        }
        __syncthreads();

        #pragma unroll 4
        for (int k = 0; k < 128; k++) {
            float xv[4];
            #pragma unroll
            for (int u = 0; u < 4; u++) xv[u] = x_s[(ty + 16 * u) * XS + k];
            float4 w0 = *(const float4*)&W_s[k * F_OUT + 4 * tx];
            float4 w1 = *(const float4*)&W_s[k * F_OUT + 64 + 4 * tx];
            float wv[8] = {w0.x, w0.y, w0.z, w0.w, w1.x, w1.y, w1.z, w1.w};
            #pragma unroll
            for (int u = 0; u < 4; u++)
                #pragma unroll
                for (int e = 0; e < 8; e++)
                    acc[u][e] += xv[u] * wv[e];
        }
    }

    #pragma unroll
    for (int u = 0; u < 4; u++) {
        float sa = 0.f, da = 0.f;
        #pragma unroll
        for (int e = 0; e < 8; e++) {
            sa += acc[u][e] * a1v[e];
            da += acc[u][e] * a2v[e];
        }
        #pragma unroll
        for (int o = 8; o; o >>= 1) {
            sa += __shfl_down_sync(0xffffffffu, sa, o, 16);
            da += __shfl_down_sync(0xffffffffu, da, o, 16);
        }
        const int r = rbase + ty + 16 * u;
        if (tx == 0) {
            g_src[r] = sa * LOG2E;
            g_dst[r] = da * LOG2E;
        }
        float4 o0, o1;
        o0.x = to_tf32(acc[u][0]); o0.y = to_tf32(acc[u][1]);
        o0.z = to_tf32(acc[u][2]); o0.w = to_tf32(acc[u][3]);
        o1.x = to_tf32(acc[u][4]); o1.y = to_tf32(acc[u][5]);
        o1.z = to_tf32(acc[u][6]); o1.w = to_tf32(acc[u][7]);
        *(float4*)&g_h[(size_t)r * F_OUT + 4 * tx]      = o0;
        *(float4*)&g_h[(size_t)r * F_OUT + 64 + 4 * tx] = o1;
    }
}

// ---------------------------------------------------------------------------
// Kernel 2: fused masked-softmax attention (tf32 mma.sync), 32 warps/SM.
// grid 512: rb = bid>>2 (64 rows), jq = bid&3 (2048 j). block 512 (16 warps),
// 2 CTAs/SM (<=64 regs). Warp tile 16x32, acc = 16 regs/thread.
// Score: 8 threads/row (adj LDG spans 4 rows/warp -> 4 L1tex wavefronts).
// ---------------------------------------------------------------------------
__global__ void __launch_bounds__(512, 2)
attn_kernel(const int* __restrict__ adj) {
    extern __shared__ float sm[];
    const int PS = 36, HS = 136;
    float* P_s = sm;                        // [64][36]
    float* h_s = sm + 64 * PS;              // [32][136]

    const int t    = threadIdx.x;
    const int rb   = blockIdx.x >> 2, jq = blockIdx.x & 3;
    const int r0   = rb * 64;
    const int jbase = jq * 2048;
    const int lane = t & 31, w = t >> 5;
    const int gID  = lane >> 2, tig = lane & 3;
    const int mw   = w & 3;                 // m-strip (16 rows)
    const int nw   = w >> 2;                // n-block (32 cols)
    const int row  = t >> 3, q = t & 7;     // score: 8 threads/row, 4 cols each

    const float srcv = g_src[r0 + row];
    float l_reg = 0.f;

    float acc[4][4];
    #pragma unroll
    for (int nt = 0; nt < 4; nt++)
        #pragma unroll
        for (int c = 0; c < 4; c++) acc[nt][c] = 0.f;

    const int*   ap = adj   + (size_t)(r0 + row) * N_NODES + jbase + q * 4;
    const float* dp = g_dst + jbase + q * 4;
    int4 adjv = *(const int4*)ap;

    for (int ch = 0; ch < NCHUNK; ch++) {
        const int j0 = ch * KC;
        __syncthreads();                    // previous MMA done with P_s / h_s

        // Stage h tile [32 j][128 f]: 2 float4 per thread, coalesced
        #pragma unroll
        for (int u = 0; u < 2; u++) {
            const int idx = t + u * 512;
            const int jr = idx >> 5, c4 = idx & 31;
            *(float4*)&h_s[jr * HS + c4 * 4] =
                *(const float4*)&g_h[(size_t)(jbase + j0 + jr) * F_OUT + c4 * 4];
        }

        // Score phase: 4 cols per thread
        {
            const float4 dv = *(const float4*)(dp + j0);
            float4 pv; float s;
            s = srcv + dv.x; s = fmaxf(s, 0.2f * s);
            pv.x = (adjv.x > 0) ? ex2(s) : 0.f;
            s = srcv + dv.y; s = fmaxf(s, 0.2f * s);
            pv.y = (adjv.y > 0) ? ex2(s) : 0.f;
            s = srcv + dv.z; s = fmaxf(s, 0.2f * s);
            pv.z = (adjv.z > 0) ? ex2(s) : 0.f;
            s = srcv + dv.w; s = fmaxf(s, 0.2f * s);
            pv.w = (adjv.w > 0) ? ex2(s) : 0.f;
            *(float4*)&P_s[row * PS + q * 4] = pv;
            float lsum = (pv.x + pv.y) + (pv.z + pv.w);
            lsum += __shfl_xor_sync(0xffffffffu, lsum, 1, 8);
            lsum += __shfl_xor_sync(0xffffffffu, lsum, 2, 8);
            lsum += __shfl_xor_sync(0xffffffffu, lsum, 4, 8);
            if (q == 0) l_reg += lsum;
        }

        // Prefetch next chunk's adj (lands during MMA phase)
        const int jn = (ch < NCHUNK - 1) ? (ch + 1) * KC : 0;
        adjv = *(const int4*)(ap + jn);

        __syncthreads();                    // P_s / h_s ready

        // MMA phase: D[64x128] += P[64x32] @ h[32x128]; warp tile 16x32
        #pragma unroll
        for (int k0 = 0; k0 < KC; k0 += 8) {
            unsigned Af[4];
            const float* pr = &P_s[(mw * 16 + gID) * PS + k0];
            Af[0] = __float_as_uint(pr[tig]);
            Af[1] = __float_as_uint(pr[8 * PS + tig]);
            Af[2] = __float_as_uint(pr[tig + 4]);
            Af[3] = __float_as_uint(pr[8 * PS + tig + 4]);
            #pragma unroll
            for (int nt = 0; nt < 4; nt++) {
                unsigned Bf[2];
                const int nc = nw * 32 + nt * 8 + gID;
                Bf[0] = __float_as_uint(h_s[(k0 + tig) * HS + nc]);
                Bf[1] = __float_as_uint(h_s[(k0 + tig + 4) * HS + nc]);
                mma_tf32(acc[nt], Af, Bf);
            }
        }
    }

    if (q == 0) g_partL[blockIdx.x * 64 + row] = l_reg;

    // Epilogue: store unnormalized partials
    const size_t dbase = (size_t)blockIdx.x * 64 * F_OUT;
    const int ra = mw * 16 + gID;
    #pragma unroll
    for (int nt = 0; nt < 4; nt++) {
        const int c = nw * 32 + nt * 8 + 2 * tig;
        float2 v0, v1;
        v0.x = acc[nt][0]; v0.y = acc[nt][1];
        v1.x = acc[nt][2]; v1.y = acc[nt][3];
        *(float2*)&g_partD[dbase + (size_t)ra * F_OUT + c]       = v0;
        *(float2*)&g_partD[dbase + (size_t)(ra + 8) * F_OUT + c] = v1;
    }
}

// ---------------------------------------------------------------------------
// Kernel 3: combine 4 j-quarters: out = sum(D_p) / sum(l_p)
// ---------------------------------------------------------------------------
__global__ void __launch_bounds__(512, 4)
combine_kernel(float* __restrict__ out) {
    const int idx  = blockIdx.x * 512 + threadIdx.x;  // 262144 float4 total
    const int rowc = idx >> 5;                        // 0..8191
    const int c4   = idx & 31;
    const int rbk  = rowc >> 6, m = rowc & 63;
    const size_t b0 = (size_t)(4 * rbk) * 64 * F_OUT + (size_t)m * F_OUT + c4 * 4;
    const float4 d0 = *(const float4*)&g_partD[b0];
    const float4 d1 = *(const float4*)&g_partD[b0 + 1 * 64 * F_OUT];
    const float4 d2 = *(const float4*)&g_partD[b0 + 2 * 64 * F_OUT];
    const float4 d3 = *(const float4*)&g_partD[b0 + 3 * 64 * F_OUT];
    const float lsum = g_partL[(4 * rbk + 0) * 64 + m] + g_partL[(4 * rbk + 1) * 64 + m]
                     + g_partL[(4 * rbk + 2) * 64 + m] + g_partL[(4 * rbk + 3) * 64 + m];
    const float inv = 1.f / lsum;
    float4 o;
    o.x = ((d0.x + d1.x) + (d2.x + d3.x)) * inv;
    o.y = ((d0.y + d1.y) + (d2.y + d3.y)) * inv;
    o.z = ((d0.z + d1.z) + (d2.z + d3.z)) * inv;
    o.w = ((d0.w + d1.w) + (d2.w + d3.w)) * inv;
    *(float4*)&out[(size_t)rowc * F_OUT + c4 * 4] = o;
}

// ---------------------------------------------------------------------------
extern "C" void kernel_launch(void* const* d_in, const int* in_sizes, int n_in,
                              void* d_out, int out_size) {
    const float* x   = (const float*)d_in[0];
    const int*   adj = (const int*)  d_in[1];
    const float* W   = (const float*)d_in[2];
    const float* a   = (const float*)d_in[3];
    float* out = (float*)d_out;

    const int A_SMEM = (128 * F_OUT + 64 * 132) * 4;            // 99,328 B
    const int B_SMEM = (64 * 36 + 32 * 136) * 4;                // 26,624 B
    cudaFuncSetAttribute(prep_kernel, cudaFuncAttributeMaxDynamicSharedMemorySize, A_SMEM);
    cudaFuncSetAttribute(attn_kernel, cudaFuncAttributeMaxDynamicSharedMemorySize, B_SMEM);

    prep_kernel<<<128, 256, A_SMEM>>>(x, W, a);
    attn_kernel<<<512, 512, B_SMEM>>>(adj);
    combine_kernel<<<512, 512>>>(out);
}

// round 7
// speedup vs baseline: 1.8718x; 1.1042x over previous
#include <cuda_runtime.h>
#include <cstdint>

#define N_NODES 8192
#define F_IN    256
#define F_OUT   128
#define KC      32      // j per chunk in attn
#define NCHUNK  64      // 2048 j per CTA / KC
#define LOG2E   1.4426950408889634f

// Scratch (device globals: no allocation allowed in kernel_launch)
__device__ float g_h[N_NODES * F_OUT];          // h = x@W, tf32-rounded, row-major
__device__ float g_src[N_NODES];                // src * log2e
__device__ float g_dst[N_NODES];                // dst * log2e
__device__ float g_partD[512 * 64 * F_OUT];     // [cta][m][f] partial P@h
__device__ float g_partL[512 * 64];             // [cta][m] partial row sums

__device__ __forceinline__ float to_tf32(float v) {
    unsigned r;
    asm("cvt.rna.tf32.f32 %0, %1;" : "=r"(r) : "f"(v));
    return __uint_as_float(r);
}
__device__ __forceinline__ float ex2(float v) {
    float r;
    asm("ex2.approx.f32 %0, %1;" : "=f"(r) : "f"(v));
    return r;
}
__device__ __forceinline__ uint32_t smem_u32(const void* p) {
    uint32_t a;
    asm("{ .reg .u64 t; cvta.to.shared.u64 t, %1; cvt.u32.u64 %0, t; }" : "=r"(a) : "l"(p));
    return a;
}
__device__ __forceinline__ void cp16(uint32_t dst, const void* src) {
    asm volatile("cp.async.cg.shared.global [%0], [%1], 16;" :: "r"(dst), "l"(src));
}
#define CP_COMMIT() asm volatile("cp.async.commit_group;")
#define CP_WAIT1()  asm volatile("cp.async.wait_group 1;")

__device__ __forceinline__ void mma_tf32(float* d, const unsigned* a, const unsigned* b) {
    asm volatile(
        "mma.sync.aligned.m16n8k8.row.col.f32.tf32.tf32.f32 "
        "{%0,%1,%2,%3}, {%4,%5,%6,%7}, {%8,%9}, {%0,%1,%2,%3};\n"
        : "+f"(d[0]), "+f"(d[1]), "+f"(d[2]), "+f"(d[3])
        : "r"(a[0]), "r"(a[1]), "r"(a[2]), "r"(a[3]), "r"(b[0]), "r"(b[1]));
}

// ---------------------------------------------------------------------------
// Kernel 1: h = x@W (fp32 exact), src/dst (scaled by log2e), h tf32-rounded.
// ---------------------------------------------------------------------------
__global__ void __launch_bounds__(256, 2)
prep_kernel(const float* __restrict__ x, const float* __restrict__ W,
            const float* __restrict__ a) {
    extern __shared__ float sm[];
    float* W_s = sm;                       // [128 k][128 f]
    float* x_s = sm + 128 * F_OUT;         // [64 rows][132]
    const int XS = 132;

    const int t  = threadIdx.x;
    const int tx = t & 15, ty = t >> 4;
    const int rbase = blockIdx.x * 64;

    float a1v[8], a2v[8];
    #pragma unroll
    for (int e = 0; e < 4; e++) {
        a1v[e]     = a[4 * tx + e];
        a1v[4 + e] = a[64 + 4 * tx + e];
        a2v[e]     = a[F_OUT + 4 * tx + e];
        a2v[4 + e] = a[F_OUT + 64 + 4 * tx + e];
    }

    float acc[4][8];
    #pragma unroll
    for (int u = 0; u < 4; u++)
        #pragma unroll
        for (int e = 0; e < 8; e++) acc[u][e] = 0.f;

    for (int kh = 0; kh < 2; kh++) {
        __syncthreads();
        for (int i = t; i < 4096; i += 256) {
            int k = i >> 5, c4 = i & 31;
            *(float4*)&W_s[k * F_OUT + c4 * 4] =
                *(const float4*)&W[(kh * 128 + k) * F_OUT + c4 * 4];
        }
        for (int i = t; i < 2048; i += 256) {
            int r = i >> 5, c4 = i & 31;
            *(float4*)&x_s[r * XS + c4 * 4] =
                *(const float4*)&x[(rbase + r) * F_IN + kh * 128 + c4 * 4];
        }
        __syncthreads();

        #pragma unroll 4
        for (int k = 0; k < 128; k++) {
            float xv[4];
            #pragma unroll
            for (int u = 0; u < 4; u++) xv[u] = x_s[(ty + 16 * u) * XS + k];
            float4 w0 = *(const float4*)&W_s[k * F_OUT + 4 * tx];
            float4 w1 = *(const float4*)&W_s[k * F_OUT + 64 + 4 * tx];
            float wv[8] = {w0.x, w0.y, w0.z, w0.w, w1.x, w1.y, w1.z, w1.w};
            #pragma unroll
            for (int u = 0; u < 4; u++)
                #pragma unroll
                for (int e = 0; e < 8; e++)
                    acc[u][e] += xv[u] * wv[e];
        }
    }

    #pragma unroll
    for (int u = 0; u < 4; u++) {
        float sa = 0.f, da = 0.f;
        #pragma unroll
        for (int e = 0; e < 8; e++) {
            sa += acc[u][e] * a1v[e];
            da += acc[u][e] * a2v[e];
        }
        #pragma unroll
        for (int o = 8; o; o >>= 1) {
            sa += __shfl_down_sync(0xffffffffu, sa, o, 16);
            da += __shfl_down_sync(0xffffffffu, da, o, 16);
        }
        const int r = rbase + ty + 16 * u;
        if (tx == 0) {
            g_src[r] = sa * LOG2E;
            g_dst[r] = da * LOG2E;
        }
        float4 o0, o1;
        o0.x = to_tf32(acc[u][0]); o0.y = to_tf32(acc[u][1]);
        o0.z = to_tf32(acc[u][2]); o0.w = to_tf32(acc[u][3]);
        o1.x = to_tf32(acc[u][4]); o1.y = to_tf32(acc[u][5]);
        o1.z = to_tf32(acc[u][6]); o1.w = to_tf32(acc[u][7]);
        *(float4*)&g_h[(size_t)r * F_OUT + 4 * tx]      = o0;
        *(float4*)&g_h[(size_t)r * F_OUT + 64 + 4 * tx] = o1;
    }
}

// ---------------------------------------------------------------------------
// Kernel 2: fused masked-softmax attention, cp.async 3-stage pipeline.
// grid 512: rb = bid>>2 (64 rows), jq = bid&3 (2048 j). block 512, 2 CTAs/SM.
// Stages hold adj/h/dst for chunk ch; all score+MMA reads hit smem only.
// ---------------------------------------------------------------------------
__global__ void __launch_bounds__(512, 2)
attn_kernel(const int* __restrict__ adj) {
    extern __shared__ float sm[];
    // float-offset layout:
    //   h_s   : 3 stages x [32][136]  -> [0, 13056)
    //   adj_s : 3 stages x [64][32]i  -> [13056, 19200)
    //   dst_s : 3 stages x [32]       -> [19200, 19296)
    //   P_s   : [64][36]              -> [19296, 21600)
    const int HST = 4352, PS = 36, HS = 136;
    float* h_s   = sm;
    int*   adj_s = (int*)(sm + 13056);
    float* dst_s = sm + 19200;
    float* P_s   = sm + 19296;

    const uint32_t sb      = smem_u32(sm);
    const uint32_t h_u     = sb;
    const uint32_t adj_u   = sb + 13056 * 4;
    const uint32_t dst_u   = sb + 19200 * 4;

    const int t    = threadIdx.x;
    const int rb   = blockIdx.x >> 2, jq = blockIdx.x & 3;
    const int r0   = rb * 64;
    const int jbase = jq * 2048;
    const int lane = t & 31, w = t >> 5;
    const int gID  = lane >> 2, tig = lane & 3;
    const int mw   = w & 3;                 // m-strip (16 rows)
    const int nw   = w >> 2;                // n-block (32 cols)
    const int row  = t >> 3, q = t & 7;     // score: 8 threads/row, 4 cols each

    const float srcv = g_src[r0 + row];
    float l_reg = 0.f;

    float acc[4][4];
    #pragma unroll
    for (int nt = 0; nt < 4; nt++)
        #pragma unroll
        for (int c = 0; c < 4; c++) acc[nt][c] = 0.f;

    // per-thread cp.async coordinates
    const int hjr0 = t >> 5,           hc0 = (t & 31) * 4;        // h part 0
    const int hjr1 = (t + 512) >> 5,   hc1 = hc0;                 // h part 1
    const float* hsrc_base = g_h + (size_t)jbase * F_OUT;
    const int*   asrc      = adj + (size_t)(r0 + row) * N_NODES + jbase + q * 4;

    // issue one full stage of cp.async for chunk `ch` into stage slot `st`
    #define ISSUE_STAGE(ch_, st_)                                              \
    {                                                                          \
        const int j0_ = (ch_) * KC;                                            \
        cp16(h_u + ((st_) * HST + hjr0 * HS + hc0) * 4,                        \
             hsrc_base + (size_t)(j0_ + hjr0) * F_OUT + hc0);                  \
        cp16(h_u + ((st_) * HST + hjr1 * HS + hc1) * 4,                        \
             hsrc_base + (size_t)(j0_ + hjr1) * F_OUT + hc1);                  \
        cp16(adj_u + ((st_) * 2048 + row * 32 + q * 4) * 4, asrc + j0_);       \
        if (t < 8)                                                             \
            cp16(dst_u + ((st_) * 32 + t * 4) * 4, g_dst + jbase + j0_ + t*4); \
    }

    // prologue: stages 0 and 1
    ISSUE_STAGE(0, 0); CP_COMMIT();
    ISSUE_STAGE(1, 1); CP_COMMIT();

    int st = 0;
    for (int ch = 0; ch < NCHUNK; ch++) {
        CP_WAIT1();                         // stage ch landed
        __syncthreads();                    // visible to all; MMA(ch-1) done

        // Score phase: adj/dst from smem
        {
            const int4 av  = *(const int4*)&adj_s[st * 2048 + row * 32 + q * 4];
            const float4 dv = *(const float4*)&dst_s[st * 32 + q * 4];
            float4 pv; float s;
            s = srcv + dv.x; s = fmaxf(s, 0.2f * s);
            pv.x = (av.x > 0) ? ex2(s) : 0.f;
            s = srcv + dv.y; s = fmaxf(s, 0.2f * s);
            pv.y = (av.y > 0) ? ex2(s) : 0.f;
            s = srcv + dv.z; s = fmaxf(s, 0.2f * s);
            pv.z = (av.z > 0) ? ex2(s) : 0.f;
            s = srcv + dv.w; s = fmaxf(s, 0.2f * s);
            pv.w = (av.w > 0) ? ex2(s) : 0.f;
            *(float4*)&P_s[row * PS + q * 4] = pv;
            float lsum = (pv.x + pv.y) + (pv.z + pv.w);
            lsum += __shfl_xor_sync(0xffffffffu, lsum, 1, 8);
            lsum += __shfl_xor_sync(0xffffffffu, lsum, 2, 8);
            lsum += __shfl_xor_sync(0xffffffffu, lsum, 4, 8);
            if (q == 0) l_reg += lsum;
        }

        // issue stage ch+2 (slot == (ch+2)%3; its previous reader MMA(ch-1)
        // finished before the barrier above)
        if (ch + 2 < NCHUNK) {
            const int stn = (st + 2 >= 3) ? st - 1 : st + 2;
            ISSUE_STAGE(ch + 2, stn);
        }
        CP_COMMIT();                        // always commit (keeps count sane)

        __syncthreads();                    // P_s ready

        // MMA phase: D[64x128] += P[64x32] @ h[32x128]; warp tile 16x32
        const float* Hc = h_s + st * HST;
        #pragma unroll
        for (int k0 = 0; k0 < KC; k0 += 8) {
            unsigned Af[4];
            const float* pr = &P_s[(mw * 16 + gID) * PS + k0];
            Af[0] = __float_as_uint(pr[tig]);
            Af[1] = __float_as_uint(pr[8 * PS + tig]);
            Af[2] = __float_as_uint(pr[tig + 4]);
            Af[3] = __float_as_uint(pr[8 * PS + tig + 4]);
            #pragma unroll
            for (int nt = 0; nt < 4; nt++) {
                unsigned Bf[2];
                const int nc = nw * 32 + nt * 8 + gID;
                Bf[0] = __float_as_uint(Hc[(k0 + tig) * HS + nc]);
                Bf[1] = __float_as_uint(Hc[(k0 + tig + 4) * HS + nc]);
                mma_tf32(acc[nt], Af, Bf);
            }
        }

        st = (st + 1 >= 3) ? 0 : st + 1;
    }

    if (q == 0) g_partL[blockIdx.x * 64 + row] = l_reg;

    // Epilogue: store unnormalized partials
    const size_t dbase = (size_t)blockIdx.x * 64 * F_OUT;
    const int ra = mw * 16 + gID;
    #pragma unroll
    for (int nt = 0; nt < 4; nt++) {
        const int c = nw * 32 + nt * 8 + 2 * tig;
        float2 v0, v1;
        v0.x = acc[nt][0]; v0.y = acc[nt][1];
        v1.x = acc[nt][2]; v1.y = acc[nt][3];
        *(float2*)&g_partD[dbase + (size_t)ra * F_OUT + c]       = v0;
        *(float2*)&g_partD[dbase + (size_t)(ra + 8) * F_OUT + c] = v1;
    }
}

// ---------------------------------------------------------------------------
// Kernel 3: combine 4 j-quarters: out = sum(D_p) / sum(l_p)
// ---------------------------------------------------------------------------
__global__ void __launch_bounds__(512, 4)
combine_kernel(float* __restrict__ out) {
    const int idx  = blockIdx.x * 512 + threadIdx.x;  // 262144 float4 total
    const int rowc = idx >> 5;                        // 0..8191
    const int c4   = idx & 31;
    const int rbk  = rowc >> 6, m = rowc & 63;
    const size_t b0 = (size_t)(4 * rbk) * 64 * F_OUT + (size_t)m * F_OUT + c4 * 4;
    const float4 d0 = *(const float4*)&g_partD[b0];
    const float4 d1 = *(const float4*)&g_partD[b0 + 1 * 64 * F_OUT];
    const float4 d2 = *(const float4*)&g_partD[b0 + 2 * 64 * F_OUT];
    const float4 d3 = *(const float4*)&g_partD[b0 + 3 * 64 * F_OUT];
    const float lsum = g_partL[(4 * rbk + 0) * 64 + m] + g_partL[(4 * rbk + 1) * 64 + m]
                     + g_partL[(4 * rbk + 2) * 64 + m] + g_partL[(4 * rbk + 3) * 64 + m];
    const float inv = 1.f / lsum;
    float4 o;
    o.x = ((d0.x + d1.x) + (d2.x + d3.x)) * inv;
    o.y = ((d0.y + d1.y) + (d2.y + d3.y)) * inv;
    o.z = ((d0.z + d1.z) + (d2.z + d3.z)) * inv;
    o.w = ((d0.w + d1.w) + (d2.w + d3.w)) * inv;
    *(float4*)&out[(size_t)rowc * F_OUT + c4 * 4] = o;
}

// ---------------------------------------------------------------------------
extern "C" void kernel_launch(void* const* d_in, const int* in_sizes, int n_in,
                              void* d_out, int out_size) {
    const float* x   = (const float*)d_in[0];
    const int*   adj = (const int*)  d_in[1];
    const float* W   = (const float*)d_in[2];
    const float* a   = (const float*)d_in[3];
    float* out = (float*)d_out;

    const int A_SMEM = (128 * F_OUT + 64 * 132) * 4;            // 99,328 B
    const int B_SMEM = 21600 * 4;                               // 86,400 B
    cudaFuncSetAttribute(prep_kernel, cudaFuncAttributeMaxDynamicSharedMemorySize, A_SMEM);
    cudaFuncSetAttribute(attn_kernel, cudaFuncAttributeMaxDynamicSharedMemorySize, B_SMEM);

    prep_kernel<<<128, 256, A_SMEM>>>(x, W, a);
    attn_kernel<<<512, 512, B_SMEM>>>(adj);
    combine_kernel<<<512, 512>>>(out);
}

// round 8
// speedup vs baseline: 2.4724x; 1.3209x over previous
#include <cuda_runtime.h>
#include <cuda_fp16.h>
#include <cstdint>

#define N_NODES 8192
#define F_IN    256
#define F_OUT   128
#define KC      32      // j per chunk in attn
#define NCHUNK  64      // 2048 j per CTA / KC
#define LOG2E   1.4426950408889634f

// Scratch (device globals: no allocation allowed in kernel_launch)
__device__ __half g_hT[F_OUT * N_NODES];        // h^T fp16: [f][j]
__device__ float g_src[N_NODES];                // src * log2e
__device__ float g_dst[N_NODES];                // dst * log2e
__device__ float g_partD[512 * 64 * F_OUT];     // [cta][m][f] partial P@h
__device__ float g_partL[512 * 64];             // [cta][m] partial row sums

__device__ __forceinline__ float ex2(float v) {
    float r;
    asm("ex2.approx.f32 %0, %1;" : "=f"(r) : "f"(v));
    return r;
}
__device__ __forceinline__ uint32_t smem_u32(const void* p) {
    uint32_t a;
    asm("{ .reg .u64 t; cvta.to.shared.u64 t, %1; cvt.u32.u64 %0, t; }" : "=r"(a) : "l"(p));
    return a;
}
__device__ __forceinline__ void cp16(uint32_t dst, const void* src) {
    asm volatile("cp.async.cg.shared.global [%0], [%1], 16;" :: "r"(dst), "l"(src));
}
#define CP_COMMIT() asm volatile("cp.async.commit_group;")
#define CP_WAIT1()  asm volatile("cp.async.wait_group 1;")

__device__ __forceinline__ void mma_f16(float* d, const unsigned* a, const unsigned* b) {
    asm volatile(
        "mma.sync.aligned.m16n8k16.row.col.f32.f16.f16.f32 "
        "{%0,%1,%2,%3}, {%4,%5,%6,%7}, {%8,%9}, {%0,%1,%2,%3};\n"
        : "+f"(d[0]), "+f"(d[1]), "+f"(d[2]), "+f"(d[3])
        : "r"(a[0]), "r"(a[1]), "r"(a[2]), "r"(a[3]), "r"(b[0]), "r"(b[1]));
}

// ---------------------------------------------------------------------------
// Kernel 1: h = x@W (fp32 exact), src/dst (scaled by log2e), h^T stored fp16.
// grid 128 (64 rows), block 256, W staged in two k-halves; smem transpose out.
// ---------------------------------------------------------------------------
__global__ void __launch_bounds__(256, 2)
prep_kernel(const float* __restrict__ x, const float* __restrict__ W,
            const float* __restrict__ a) {
    extern __shared__ float sm[];
    float* W_s = sm;                       // [128 k][128 f]
    float* x_s = sm + 128 * F_OUT;         // [64 rows][132]
    __half* hT_tile = (__half*)(sm + 128 * F_OUT);  // [128 f][72] (aliases x_s)
    const int XS = 132;

    const int t  = threadIdx.x;
    const int tx = t & 15, ty = t >> 4;
    const int rbase = blockIdx.x * 64;

    float a1v[8], a2v[8];
    #pragma unroll
    for (int e = 0; e < 4; e++) {
        a1v[e]     = a[4 * tx + e];
        a1v[4 + e] = a[64 + 4 * tx + e];
        a2v[e]     = a[F_OUT + 4 * tx + e];
        a2v[4 + e] = a[F_OUT + 64 + 4 * tx + e];
    }

    float acc[4][8];
    #pragma unroll
    for (int u = 0; u < 4; u++)
        #pragma unroll
        for (int e = 0; e < 8; e++) acc[u][e] = 0.f;

    for (int kh = 0; kh < 2; kh++) {
        __syncthreads();
        for (int i = t; i < 4096; i += 256) {
            int k = i >> 5, c4 = i & 31;
            *(float4*)&W_s[k * F_OUT + c4 * 4] =
                *(const float4*)&W[(kh * 128 + k) * F_OUT + c4 * 4];
        }
        for (int i = t; i < 2048; i += 256) {
            int r = i >> 5, c4 = i & 31;
            *(float4*)&x_s[r * XS + c4 * 4] =
                *(const float4*)&x[(rbase + r) * F_IN + kh * 128 + c4 * 4];
        }
        __syncthreads();

        #pragma unroll 4
        for (int k = 0; k < 128; k++) {
            float xv[4];
            #pragma unroll
            for (int u = 0; u < 4; u++) xv[u] = x_s[(ty + 16 * u) * XS + k];
            float4 w0 = *(const float4*)&W_s[k * F_OUT + 4 * tx];
            float4 w1 = *(const float4*)&W_s[k * F_OUT + 64 + 4 * tx];
            float wv[8] = {w0.x, w0.y, w0.z, w0.w, w1.x, w1.y, w1.z, w1.w};
            #pragma unroll
            for (int u = 0; u < 4; u++)
                #pragma unroll
                for (int e = 0; e < 8; e++)
                    acc[u][e] += xv[u] * wv[e];
        }
    }

    #pragma unroll
    for (int u = 0; u < 4; u++) {
        float sa = 0.f, da = 0.f;
        #pragma unroll
        for (int e = 0; e < 8; e++) {
            sa += acc[u][e] * a1v[e];
            da += acc[u][e] * a2v[e];
        }
        #pragma unroll
        for (int o = 8; o; o >>= 1) {
            sa += __shfl_down_sync(0xffffffffu, sa, o, 16);
            da += __shfl_down_sync(0xffffffffu, da, o, 16);
        }
        const int r = rbase + ty + 16 * u;
        if (tx == 0) {
            g_src[r] = sa * LOG2E;
            g_dst[r] = da * LOG2E;
        }
    }

    // Transpose h into smem fp16 tile [128 f][72-stride], then coalesced out
    __syncthreads();   // all x_s reads done
    #pragma unroll
    for (int u = 0; u < 4; u++) {
        const int col = ty + 16 * u;   // j within tile
        #pragma unroll
        for (int e = 0; e < 4; e++) {
            hT_tile[(4 * tx + e) * 72 + col]      = __float2half_rn(acc[u][e]);
            hT_tile[(64 + 4 * tx + e) * 72 + col] = __float2half_rn(acc[u][4 + e]);
        }
    }
    __syncthreads();
    // 128 f-rows x 64 halves = 1024 float4
    #pragma unroll
    for (int i = 0; i < 4; i++) {
        const int idx = t + i * 256;
        const int f = idx >> 3, seg = idx & 7;
        float4 v = *(const float4*)&hT_tile[f * 72 + seg * 8];
        *(float4*)&g_hT[(size_t)f * N_NODES + rbase + seg * 8] = v;
    }
}

// ---------------------------------------------------------------------------
// Kernel 2: fused masked-softmax attention, fp16 MMA + cp.async 3-stage pipe.
// grid 512: rb = bid>>2 (64 rows), jq = bid&3 (2048 j). block 512, 2 CTAs/SM.
// P scaled by 2^-4 (softmax-invariant) to stay far from fp16 max.
// ---------------------------------------------------------------------------
__global__ void __launch_bounds__(512, 2)
attn_kernel(const int* __restrict__ adj) {
    extern __shared__ float sm[];
    // 4B-unit layout:
    //   h2_s  : 3 stages x [128 n][20 half2]  -> [0, 7680)
    //   adj_s : 3 stages x [64][32] int       -> [7680, 13824)
    //   dst_s : 3 stages x [32] float         -> [13824, 13920)
    //   P2_s  : [64 m][20 half2]              -> [13920, 15200)
    const int HST2 = 2560;                  // half2 per h stage
    __half2* h2_s  = (__half2*)sm;
    int*     adj_s = (int*)(sm + 7680);
    float*   dst_s = sm + 13824;
    __half2* P2_s  = (__half2*)(sm + 13920);

    const uint32_t sb    = smem_u32(sm);
    const uint32_t h_u   = sb;
    const uint32_t adj_u = sb + 7680 * 4;
    const uint32_t dst_u = sb + 13824 * 4;

    const int t    = threadIdx.x;
    const int rb   = blockIdx.x >> 2, jq = blockIdx.x & 3;
    const int r0   = rb * 64;
    const int jbase = jq * 2048;
    const int lane = t & 31, w = t >> 5;
    const int gID  = lane >> 2, tig = lane & 3;
    const int mw   = w & 3;                 // m-strip (16 rows)
    const int nw   = w >> 2;                // n-block (32 cols)
    const int row  = t >> 3, q = t & 7;     // score: 8 threads/row, 4 cols each

    const float srcv = g_src[r0 + row] - 4.0f;   // exponent shift folded in
    float l_reg = 0.f;

    float acc[4][4];
    #pragma unroll
    for (int nt = 0; nt < 4; nt++)
        #pragma unroll
        for (int c = 0; c < 4; c++) acc[nt][c] = 0.f;

    // cp.async coordinates
    const int hn  = t >> 2, hseg = t & 3;                 // h: 128 n x 4 segs
    const __half* hsrc = g_hT + (size_t)hn * N_NODES + jbase + hseg * 8;
    const int*    asrc = adj + (size_t)(r0 + row) * N_NODES + jbase + q * 4;

    #define ISSUE_STAGE(ch_, st_)                                              \
    {                                                                          \
        const int j0_ = (ch_) * KC;                                            \
        cp16(h_u + ((st_) * HST2 + hn * 20 + hseg * 4) * 4, hsrc + j0_);       \
        cp16(adj_u + ((st_) * 2048 + row * 32 + q * 4) * 4, asrc + j0_);       \
        if (t < 8)                                                             \
            cp16(dst_u + ((st_) * 32 + t * 4) * 4, g_dst + jbase + j0_ + t*4); \
    }

    ISSUE_STAGE(0, 0); CP_COMMIT();
    ISSUE_STAGE(1, 1); CP_COMMIT();

    int st = 0;
    for (int ch = 0; ch < NCHUNK; ch++) {
        CP_WAIT1();                         // stage ch landed
        __syncthreads();                    // visible; MMA(ch-1) done

        // Score phase: 4 cols/thread, write P as half2 pair (A-frag layout)
        {
            const int4  av = *(const int4*)&adj_s[st * 2048 + row * 32 + q * 4];
            const float4 dv = *(const float4*)&dst_s[st * 32 + q * 4];
            float4 pv; float s;
            s = srcv + dv.x; s = fmaxf(s, 0.2f * s - 3.2f);
            pv.x = (av.x > 0) ? ex2(s) : 0.f;
            s = srcv + dv.y; s = fmaxf(s, 0.2f * s - 3.2f);
            pv.y = (av.y > 0) ? ex2(s) : 0.f;
            s = srcv + dv.z; s = fmaxf(s, 0.2f * s - 3.2f);
            pv.z = (av.z > 0) ? ex2(s) : 0.f;
            s = srcv + dv.w; s = fmaxf(s, 0.2f * s - 3.2f);
            pv.w = (av.w > 0) ? ex2(s) : 0.f;
            // leaky_relu on shifted arg: max(s', 0.2*s'-3.2) == leaky(s)-4
            __half2 p01 = __floats2half2_rn(pv.x, pv.y);
            __half2 p23 = __floats2half2_rn(pv.z, pv.w);
            *(uint2*)&P2_s[row * 20 + q * 2] =
                make_uint2(*(uint32_t*)&p01, *(uint32_t*)&p23);
            float lsum = (pv.x + pv.y) + (pv.z + pv.w);
            lsum += __shfl_xor_sync(0xffffffffu, lsum, 1, 8);
            lsum += __shfl_xor_sync(0xffffffffu, lsum, 2, 8);
            lsum += __shfl_xor_sync(0xffffffffu, lsum, 4, 8);
            if (q == 0) l_reg += lsum;
        }

        if (ch + 2 < NCHUNK) {
            const int stn = (st + 2 >= 3) ? st - 1 : st + 2;
            ISSUE_STAGE(ch + 2, stn);
        }
        CP_COMMIT();

        __syncthreads();                    // P2_s ready

        // MMA phase: D[64x128] += P[64x32] @ h[32x128]; fp16 m16n8k16
        const __half2* Hc = h2_s + st * HST2;
        #pragma unroll
        for (int ks = 0; ks < 2; ks++) {
            unsigned Af[4];
            const __half2* pr = P2_s + (mw * 16 + gID) * 20 + ks * 8;
            Af[0] = *(const uint32_t*)&pr[tig];
            Af[1] = *(const uint32_t*)&pr[8 * 20 + tig];
            Af[2] = *(const uint32_t*)&pr[tig + 4];
            Af[3] = *(const uint32_t*)&pr[8 * 20 + tig + 4];
            #pragma unroll
            for (int nt = 0; nt < 4; nt++) {
                const int nc = nw * 32 + nt * 8 + gID;
                const __half2* hb = Hc + nc * 20 + ks * 8;
                unsigned Bf[2];
                Bf[0] = *(const uint32_t*)&hb[tig];
                Bf[1] = *(const uint32_t*)&hb[tig + 4];
                mma_f16(acc[nt], Af, Bf);
            }
        }

        st = (st + 1 >= 3) ? 0 : st + 1;
    }

    if (q == 0) g_partL[blockIdx.x * 64 + row] = l_reg;

    // Epilogue: store unnormalized partials
    const size_t dbase = (size_t)blockIdx.x * 64 * F_OUT;
    const int ra = mw * 16 + gID;
    #pragma unroll
    for (int nt = 0; nt < 4; nt++) {
        const int c = nw * 32 + nt * 8 + 2 * tig;
        float2 v0, v1;
        v0.x = acc[nt][0]; v0.y = acc[nt][1];
        v1.x = acc[nt][2]; v1.y = acc[nt][3];
        *(float2*)&g_partD[dbase + (size_t)ra * F_OUT + c]       = v0;
        *(float2*)&g_partD[dbase + (size_t)(ra + 8) * F_OUT + c] = v1;
    }
}

// ---------------------------------------------------------------------------
// Kernel 3: combine 4 j-quarters: out = sum(D_p) / sum(l_p)
// ---------------------------------------------------------------------------
__global__ void __launch_bounds__(512, 4)
combine_kernel(float* __restrict__ out) {
    const int idx  = blockIdx.x * 512 + threadIdx.x;  // 262144 float4 total
    const int rowc = idx >> 5;                        // 0..8191
    const int c4   = idx & 31;
    const int rbk  = rowc >> 6, m = rowc & 63;
    const size_t b0 = (size_t)(4 * rbk) * 64 * F_OUT + (size_t)m * F_OUT + c4 * 4;
    const float4 d0 = *(const float4*)&g_partD[b0];
    const float4 d1 = *(const float4*)&g_partD[b0 + 1 * 64 * F_OUT];
    const float4 d2 = *(const float4*)&g_partD[b0 + 2 * 64 * F_OUT];
    const float4 d3 = *(const float4*)&g_partD[b0 + 3 * 64 * F_OUT];
    const float lsum = g_partL[(4 * rbk + 0) * 64 + m] + g_partL[(4 * rbk + 1) * 64 + m]
                     + g_partL[(4 * rbk + 2) * 64 + m] + g_partL[(4 * rbk + 3) * 64 + m];
    const float inv = 1.f / lsum;
    float4 o;
    o.x = ((d0.x + d1.x) + (d2.x + d3.x)) * inv;
    o.y = ((d0.y + d1.y) + (d2.y + d3.y)) * inv;
    o.z = ((d0.z + d1.z) + (d2.z + d3.z)) * inv;
    o.w = ((d0.w + d1.w) + (d2.w + d3.w)) * inv;
    *(float4*)&out[(size_t)rowc * F_OUT + c4 * 4] = o;
}

// ---------------------------------------------------------------------------
extern "C" void kernel_launch(void* const* d_in, const int* in_sizes, int n_in,
                              void* d_out, int out_size) {
    const float* x   = (const float*)d_in[0];
    const int*   adj = (const int*)  d_in[1];
    const float* W   = (const float*)d_in[2];
    const float* a   = (const float*)d_in[3];
    float* out = (float*)d_out;

    const int A_SMEM = (128 * F_OUT + 64 * 132) * 4;            // 99,328 B
    const int B_SMEM = 15200 * 4;                               // 60,800 B
    cudaFuncSetAttribute(prep_kernel, cudaFuncAttributeMaxDynamicSharedMemorySize, A_SMEM);
    cudaFuncSetAttribute(attn_kernel, cudaFuncAttributeMaxDynamicSharedMemorySize, B_SMEM);

    prep_kernel<<<128, 256, A_SMEM>>>(x, W, a);
    attn_kernel<<<512, 512, B_SMEM>>>(adj);
    combine_kernel<<<512, 512>>>(out);
}

// round 9
// speedup vs baseline: 2.6596x; 1.0757x over previous
#include <cuda_runtime.h>
#include <cuda_fp16.h>
#include <cstdint>

#define N_NODES 8192
#define F_IN    256
#define F_OUT   128
#define KC      32      // j per chunk in attn
#define NCHUNK  64      // 2048 j per CTA / KC
#define LOG2E   1.4426950408889634f

// Named barrier IDs (0 reserved for __syncthreads)
#define FULL0 1
#define FREE0 3

__device__ __half g_hT[F_OUT * N_NODES];        // h^T fp16: [f][j]
__device__ float g_src[N_NODES];                // src * log2e
__device__ float g_dst[N_NODES];                // dst * log2e
__device__ float g_partD[512 * 64 * F_OUT];     // [cta][m][f] partial P@h
__device__ float g_partL[512 * 64];             // [cta][m] partial row sums

__device__ __forceinline__ float ex2(float v) {
    float r;
    asm("ex2.approx.f32 %0, %1;" : "=f"(r) : "f"(v));
    return r;
}
__device__ __forceinline__ uint32_t smem_u32(const void* p) {
    uint32_t a;
    asm("{ .reg .u64 t; cvta.to.shared.u64 t, %1; cvt.u32.u64 %0, t; }" : "=r"(a) : "l"(p));
    return a;
}
__device__ __forceinline__ void cp16(uint32_t dst, const void* src) {
    asm volatile("cp.async.cg.shared.global [%0], [%1], 16;" :: "r"(dst), "l"(src));
}
#define CP_COMMIT() asm volatile("cp.async.commit_group;")
#define CP_WAIT1()  asm volatile("cp.async.wait_group 1;")
#define BAR_SYNC(id)   asm volatile("bar.sync %0, 512;"   :: "r"(id) : "memory")
#define BAR_ARRIVE(id) asm volatile("bar.arrive %0, 512;" :: "r"(id) : "memory")

__device__ __forceinline__ void mma_f16(float* d, const unsigned* a, const unsigned* b) {
    asm volatile(
        "mma.sync.aligned.m16n8k16.row.col.f32.f16.f16.f32 "
        "{%0,%1,%2,%3}, {%4,%5,%6,%7}, {%8,%9}, {%0,%1,%2,%3};\n"
        : "+f"(d[0]), "+f"(d[1]), "+f"(d[2]), "+f"(d[3])
        : "r"(a[0]), "r"(a[1]), "r"(a[2]), "r"(a[3]), "r"(b[0]), "r"(b[1]));
}

// ---------------------------------------------------------------------------
// Kernel 1: h = x@W (fp32 exact), src/dst (scaled by log2e), h^T stored fp16.
// ---------------------------------------------------------------------------
__global__ void __launch_bounds__(256, 2)
prep_kernel(const float* __restrict__ x, const float* __restrict__ W,
            const float* __restrict__ a) {
    extern __shared__ float sm[];
    float* W_s = sm;                       // [128 k][128 f]
    float* x_s = sm + 128 * F_OUT;         // [64 rows][132]
    __half* hT_tile = (__half*)(sm + 128 * F_OUT);  // [128 f][72] (aliases x_s)
    const int XS = 132;

    const int t  = threadIdx.x;
    const int tx = t & 15, ty = t >> 4;
    const int rbase = blockIdx.x * 64;

    float a1v[8], a2v[8];
    #pragma unroll
    for (int e = 0; e < 4; e++) {
        a1v[e]     = a[4 * tx + e];
        a1v[4 + e] = a[64 + 4 * tx + e];
        a2v[e]     = a[F_OUT + 4 * tx + e];
        a2v[4 + e] = a[F_OUT + 64 + 4 * tx + e];
    }

    float acc[4][8];
    #pragma unroll
    for (int u = 0; u < 4; u++)
        #pragma unroll
        for (int e = 0; e < 8; e++) acc[u][e] = 0.f;

    for (int kh = 0; kh < 2; kh++) {
        __syncthreads();
        for (int i = t; i < 4096; i += 256) {
            int k = i >> 5, c4 = i & 31;
            *(float4*)&W_s[k * F_OUT + c4 * 4] =
                *(const float4*)&W[(kh * 128 + k) * F_OUT + c4 * 4];
        }
        for (int i = t; i < 2048; i += 256) {
            int r = i >> 5, c4 = i & 31;
            *(float4*)&x_s[r * XS + c4 * 4] =
                *(const float4*)&x[(rbase + r) * F_IN + kh * 128 + c4 * 4];
        }
        __syncthreads();

        #pragma unroll 4
        for (int k = 0; k < 128; k++) {
            float xv[4];
            #pragma unroll
            for (int u = 0; u < 4; u++) xv[u] = x_s[(ty + 16 * u) * XS + k];
            float4 w0 = *(const float4*)&W_s[k * F_OUT + 4 * tx];
            float4 w1 = *(const float4*)&W_s[k * F_OUT + 64 + 4 * tx];
            float wv[8] = {w0.x, w0.y, w0.z, w0.w, w1.x, w1.y, w1.z, w1.w};
            #pragma unroll
            for (int u = 0; u < 4; u++)
                #pragma unroll
                for (int e = 0; e < 8; e++)
                    acc[u][e] += xv[u] * wv[e];
        }
    }

    #pragma unroll
    for (int u = 0; u < 4; u++) {
        float sa = 0.f, da = 0.f;
        #pragma unroll
        for (int e = 0; e < 8; e++) {
            sa += acc[u][e] * a1v[e];
            da += acc[u][e] * a2v[e];
        }
        #pragma unroll
        for (int o = 8; o; o >>= 1) {
            sa += __shfl_down_sync(0xffffffffu, sa, o, 16);
            da += __shfl_down_sync(0xffffffffu, da, o, 16);
        }
        const int r = rbase + ty + 16 * u;
        if (tx == 0) {
            g_src[r] = sa * LOG2E;
            g_dst[r] = da * LOG2E;
        }
    }

    __syncthreads();   // all x_s reads done
    #pragma unroll
    for (int u = 0; u < 4; u++) {
        const int col = ty + 16 * u;
        #pragma unroll
        for (int e = 0; e < 4; e++) {
            hT_tile[(4 * tx + e) * 72 + col]      = __float2half_rn(acc[u][e]);
            hT_tile[(64 + 4 * tx + e) * 72 + col] = __float2half_rn(acc[u][4 + e]);
        }
    }
    __syncthreads();
    #pragma unroll
    for (int i = 0; i < 4; i++) {
        const int idx = t + i * 256;
        const int f = idx >> 3, seg = idx & 7;
        float4 v = *(const float4*)&hT_tile[f * 72 + seg * 8];
        *(float4*)&g_hT[(size_t)f * N_NODES + rbase + seg * 8] = v;
    }
}

// ---------------------------------------------------------------------------
// Kernel 2: warp-specialized fused masked-softmax attention.
// grid 512: rb = bid>>2 (64 rows), jq = bid&3 (2048 j). block 512, 2 CTAs/SM.
// Warps 0-7: producers (scores -> double-buffered P, adj reg-prefetch).
// Warps 8-15: consumers (3-stage cp.async h pipe + fp16 MMA, tile 16x64).
// ---------------------------------------------------------------------------
__global__ void __launch_bounds__(512, 2)
attn_kernel(const int* __restrict__ adj) {
    extern __shared__ float sm[];
    // 4B-unit layout:
    //   h2_s : 3 stages x [128 n][20 half2] -> [0, 7680)
    //   P2_s : 2 bufs   x [64 m][20 half2]  -> [7680, 10240)
    //   dst_s: [2048]                        -> [10240, 12288)
    __half2* h2_s = (__half2*)sm;
    __half2* P2_s = (__half2*)(sm + 7680);
    float*   dst_s = sm + 10240;
    const uint32_t h_u = smem_u32(sm);

    const int t    = threadIdx.x;
    const int rb   = blockIdx.x >> 2, jq = blockIdx.x & 3;
    const int r0   = rb * 64;
    const int jbase = jq * 2048;
    const int w    = t >> 5;

    // Stage dst for this CTA's 2048 j once (L2-hot, read many times)
    *(float4*)&dst_s[t * 4] = *(const float4*)&g_dst[jbase + t * 4];
    __syncthreads();

    if (w < 8) {
        // ================= PRODUCER =================
        const int row = t >> 2, q = t & 3;          // 64 rows x 4 groups, 8 j each
        const int* asrc = adj + (size_t)(r0 + row) * N_NODES + jbase + q * 8;
        const float srcv = g_src[r0 + row] - 4.0f;  // exponent shift folded in
        float l_reg = 0.f;

        int4 adjv[2][2];
        #pragma unroll
        for (int s = 0; s < 2; s++) {
            adjv[s][0] = *(const int4*)(asrc + s * KC);
            adjv[s][1] = *(const int4*)(asrc + s * KC + 4);
        }

        #pragma unroll 2
        for (int ch = 0; ch < NCHUNK; ch++) {
            const int slot = ch & 1;
            if (ch >= 2) BAR_SYNC(FREE0 + slot);    // consumers done with P(slot)

            __half2* Pb = P2_s + slot * 1280;
            float lsum = 0.f;
            uint4 pk;
            #pragma unroll
            for (int i = 0; i < 2; i++) {
                const int4 av = adjv[slot][i];
                const float4 dv = *(const float4*)&dst_s[ch * KC + q * 8 + i * 4];
                float s0, s1, s2, s3;
                s0 = srcv + dv.x; s0 = fmaxf(s0, 0.2f * s0 - 3.2f);
                s1 = srcv + dv.y; s1 = fmaxf(s1, 0.2f * s1 - 3.2f);
                s2 = srcv + dv.z; s2 = fmaxf(s2, 0.2f * s2 - 3.2f);
                s3 = srcv + dv.w; s3 = fmaxf(s3, 0.2f * s3 - 3.2f);
                float p0 = (av.x > 0) ? ex2(s0) : 0.f;
                float p1 = (av.y > 0) ? ex2(s1) : 0.f;
                float p2 = (av.z > 0) ? ex2(s2) : 0.f;
                float p3 = (av.w > 0) ? ex2(s3) : 0.f;
                lsum += (p0 + p1) + (p2 + p3);
                __half2 h01 = __floats2half2_rn(p0, p1);
                __half2 h23 = __floats2half2_rn(p2, p3);
                if (i == 0) { pk.x = *(uint32_t*)&h01; pk.y = *(uint32_t*)&h23; }
                else        { pk.z = *(uint32_t*)&h01; pk.w = *(uint32_t*)&h23; }
            }
            *(uint4*)&Pb[row * 20 + q * 4] = pk;

            BAR_ARRIVE(FULL0 + slot);               // P(slot) ready

            if (ch + 2 < NCHUNK) {                  // refill reg prefetch
                adjv[slot][0] = *(const int4*)(asrc + (ch + 2) * KC);
                adjv[slot][1] = *(const int4*)(asrc + (ch + 2) * KC + 4);
            }
            lsum += __shfl_xor_sync(0xffffffffu, lsum, 1, 4);
            lsum += __shfl_xor_sync(0xffffffffu, lsum, 2, 4);
            if (q == 0) l_reg += lsum;
        }
        if (q == 0) g_partL[blockIdx.x * 64 + row] = l_reg;

    } else {
        // ================= CONSUMER =================
        const int tc   = t - 256;
        const int lane = t & 31, wc = w - 8;
        const int gID  = lane >> 2, tig = lane & 3;
        const int mw   = wc & 3;                    // m-strip (16 rows)
        const int nw   = wc >> 2;                   // n-half (64 cols)

        float acc[8][4];
        #pragma unroll
        for (int nt = 0; nt < 8; nt++)
            #pragma unroll
            for (int c = 0; c < 4; c++) acc[nt][c] = 0.f;

        // h cp.async coordinates: 128 n-rows x 32 halves, 2 threads/row
        const int hn = tc >> 1, hseg = tc & 1;
        const __half* hsrc = g_hT + (size_t)hn * N_NODES + jbase + hseg * 16;
        const uint32_t hdst = h_u + (hn * 20 + hseg * 8) * 4;

        #define ISSUE_H(ch_, stoff_)                                   \
        {                                                              \
            cp16(hdst + (stoff_), hsrc + (ch_) * KC);                  \
            cp16(hdst + (stoff_) + 16, hsrc + (ch_) * KC + 8);         \
        }

        ISSUE_H(0, 0);       CP_COMMIT();
        ISSUE_H(1, 2560 * 4); CP_COMMIT();

        int st = 0;
        #pragma unroll 2
        for (int ch = 0; ch < NCHUNK; ch++) {
            const int slot = ch & 1;
            CP_WAIT1();                             // h(ch) landed (this thread)
            BAR_SYNC(FULL0 + slot);                 // P ready + h visible + peers past MMA(ch-1)

            if (ch + 2 < NCHUNK) {
                const int stn = (st + 2 >= 3) ? st - 1 : st + 2;
                ISSUE_H(ch + 2, stn * 2560 * 4);
            }
            CP_COMMIT();

            // MMA: D[64x128] += P[64x32] @ h[32x128]; warp tile 16x64
            const __half2* Pc = P2_s + slot * 1280 + (mw * 16 + gID) * 20;
            const __half2* Hc = h2_s + st * 2560;
            #pragma unroll
            for (int ks = 0; ks < 2; ks++) {
                unsigned Af[4];
                const __half2* pr = Pc + ks * 8;
                Af[0] = *(const uint32_t*)&pr[tig];
                Af[1] = *(const uint32_t*)&pr[8 * 20 + tig];
                Af[2] = *(const uint32_t*)&pr[tig + 4];
                Af[3] = *(const uint32_t*)&pr[8 * 20 + tig + 4];
                #pragma unroll
                for (int nt = 0; nt < 8; nt++) {
                    const int nc = nw * 64 + nt * 8 + gID;
                    const __half2* hb = Hc + nc * 20 + ks * 8;
                    unsigned Bf[2];
                    Bf[0] = *(const uint32_t*)&hb[tig];
                    Bf[1] = *(const uint32_t*)&hb[tig + 4];
                    mma_f16(acc[nt], Af, Bf);
                }
            }

            if (ch + 2 < NCHUNK) BAR_ARRIVE(FREE0 + slot);  // P(slot) consumed
            st = (st + 1 >= 3) ? 0 : st + 1;
        }

        // Epilogue: store unnormalized partials
        const size_t dbase = (size_t)blockIdx.x * 64 * F_OUT;
        const int ra = mw * 16 + gID;
        #pragma unroll
        for (int nt = 0; nt < 8; nt++) {
            const int c = nw * 64 + nt * 8 + 2 * tig;
            float2 v0, v1;
            v0.x = acc[nt][0]; v0.y = acc[nt][1];
            v1.x = acc[nt][2]; v1.y = acc[nt][3];
            *(float2*)&g_partD[dbase + (size_t)ra * F_OUT + c]       = v0;
            *(float2*)&g_partD[dbase + (size_t)(ra + 8) * F_OUT + c] = v1;
        }
    }
}

// ---------------------------------------------------------------------------
// Kernel 3: combine 4 j-quarters: out = sum(D_p) / sum(l_p)
// ---------------------------------------------------------------------------
__global__ void __launch_bounds__(512, 4)
combine_kernel(float* __restrict__ out) {
    const int idx  = blockIdx.x * 512 + threadIdx.x;
    const int rowc = idx >> 5;
    const int c4   = idx & 31;
    const int rbk  = rowc >> 6, m = rowc & 63;
    const size_t b0 = (size_t)(4 * rbk) * 64 * F_OUT + (size_t)m * F_OUT + c4 * 4;
    const float4 d0 = *(const float4*)&g_partD[b0];
    const float4 d1 = *(const float4*)&g_partD[b0 + 1 * 64 * F_OUT];
    const float4 d2 = *(const float4*)&g_partD[b0 + 2 * 64 * F_OUT];
    const float4 d3 = *(const float4*)&g_partD[b0 + 3 * 64 * F_OUT];
    const float lsum = g_partL[(4 * rbk + 0) * 64 + m] + g_partL[(4 * rbk + 1) * 64 + m]
                     + g_partL[(4 * rbk + 2) * 64 + m] + g_partL[(4 * rbk + 3) * 64 + m];
    const float inv = 1.f / lsum;
    float4 o;
    o.x = ((d0.x + d1.x) + (d2.x + d3.x)) * inv;
    o.y = ((d0.y + d1.y) + (d2.y + d3.y)) * inv;
    o.z = ((d0.z + d1.z) + (d2.z + d3.z)) * inv;
    o.w = ((d0.w + d1.w) + (d2.w + d3.w)) * inv;
    *(float4*)&out[(size_t)rowc * F_OUT + c4 * 4] = o;
}

// ---------------------------------------------------------------------------
extern "C" void kernel_launch(void* const* d_in, const int* in_sizes, int n_in,
                              void* d_out, int out_size) {
    const float* x   = (const float*)d_in[0];
    const int*   adj = (const int*)  d_in[1];
    const float* W   = (const float*)d_in[2];
    const float* a   = (const float*)d_in[3];
    float* out = (float*)d_out;

    const int A_SMEM = (128 * F_OUT + 64 * 132) * 4;            // 99,328 B
    const int B_SMEM = 12288 * 4;                               // 49,152 B
    cudaFuncSetAttribute(prep_kernel, cudaFuncAttributeMaxDynamicSharedMemorySize, A_SMEM);
    cudaFuncSetAttribute(attn_kernel, cudaFuncAttributeMaxDynamicSharedMemorySize, B_SMEM);

    prep_kernel<<<128, 256, A_SMEM>>>(x, W, a);
    attn_kernel<<<512, 512, B_SMEM>>>(adj);
    combine_kernel<<<512, 512>>>(out);
}

// round 10
// speedup vs baseline: 3.0528x; 1.1478x over previous
#include <cuda_runtime.h>
#include <cuda_fp16.h>
#include <cstdint>

#define N_NODES 8192
#define F_IN    256
#define F_OUT   128
#define KC      32      // j per chunk in attn
#define NCHUNK  64      // 2048 j per CTA / KC
#define LOG2E   1.4426950408889634f

// Named barrier IDs (0 reserved for __syncthreads)
#define FULL0 1
#define FREE0 3

__device__ __half g_hT[F_OUT * N_NODES];        // h^T fp16: [f][j]
__device__ float g_src[N_NODES];                // src * log2e
__device__ float g_dst[N_NODES];                // dst * log2e
__device__ float g_partD[512 * 64 * F_OUT];     // [cta][m][f] partial P@h
__device__ float g_partL[512 * 64];             // [cta][m] partial row sums

__device__ __forceinline__ float ex2(float v) {
    float r;
    asm("ex2.approx.f32 %0, %1;" : "=f"(r) : "f"(v));
    return r;
}
__device__ __forceinline__ uint32_t smem_u32(const void* p) {
    uint32_t a;
    asm("{ .reg .u64 t; cvta.to.shared.u64 t, %1; cvt.u32.u64 %0, t; }" : "=r"(a) : "l"(p));
    return a;
}
__device__ __forceinline__ void cp16(uint32_t dst, const void* src) {
    asm volatile("cp.async.cg.shared.global [%0], [%1], 16;" :: "r"(dst), "l"(src));
}
#define CP_COMMIT() asm volatile("cp.async.commit_group;")
#define CP_WAIT1()  asm volatile("cp.async.wait_group 1;")
#define BAR_SYNC(id)   asm volatile("bar.sync %0, 512;"   :: "r"(id) : "memory")
#define BAR_ARRIVE(id) asm volatile("bar.arrive %0, 512;" :: "r"(id) : "memory")

__device__ __forceinline__ void mma_f16(float* d, const unsigned* a, const unsigned* b) {
    asm volatile(
        "mma.sync.aligned.m16n8k16.row.col.f32.f16.f16.f32 "
        "{%0,%1,%2,%3}, {%4,%5,%6,%7}, {%8,%9}, {%0,%1,%2,%3};\n"
        : "+f"(d[0]), "+f"(d[1]), "+f"(d[2]), "+f"(d[3])
        : "r"(a[0]), "r"(a[1]), "r"(a[2]), "r"(a[3]), "r"(b[0]), "r"(b[1]));
}
__device__ __forceinline__ void ldsm_x4(unsigned* r, uint32_t addr) {
    asm volatile(
        "ldmatrix.sync.aligned.m8n8.x4.shared.b16 {%0,%1,%2,%3}, [%4];"
        : "=r"(r[0]), "=r"(r[1]), "=r"(r[2]), "=r"(r[3]) : "r"(addr));
}

// ---------------------------------------------------------------------------
// Kernel 1: h = x@W (fp32 exact), src/dst (scaled by log2e), h^T stored fp16.
// ---------------------------------------------------------------------------
__global__ void __launch_bounds__(256, 2)
prep_kernel(const float* __restrict__ x, const float* __restrict__ W,
            const float* __restrict__ a) {
    extern __shared__ float sm[];
    float* W_s = sm;                       // [128 k][128 f]
    float* x_s = sm + 128 * F_OUT;         // [64 rows][132]
    __half* hT_tile = (__half*)(sm + 128 * F_OUT);  // [128 f][72] (aliases x_s)
    const int XS = 132;

    const int t  = threadIdx.x;
    const int tx = t & 15, ty = t >> 4;
    const int rbase = blockIdx.x * 64;

    float a1v[8], a2v[8];
    #pragma unroll
    for (int e = 0; e < 4; e++) {
        a1v[e]     = a[4 * tx + e];
        a1v[4 + e] = a[64 + 4 * tx + e];
        a2v[e]     = a[F_OUT + 4 * tx + e];
        a2v[4 + e] = a[F_OUT + 64 + 4 * tx + e];
    }

    float acc[4][8];
    #pragma unroll
    for (int u = 0; u < 4; u++)
        #pragma unroll
        for (int e = 0; e < 8; e++) acc[u][e] = 0.f;

    for (int kh = 0; kh < 2; kh++) {
        __syncthreads();
        for (int i = t; i < 4096; i += 256) {
            int k = i >> 5, c4 = i & 31;
            *(float4*)&W_s[k * F_OUT + c4 * 4] =
                *(const float4*)&W[(kh * 128 + k) * F_OUT + c4 * 4];
        }
        for (int i = t; i < 2048; i += 256) {
            int r = i >> 5, c4 = i & 31;
            *(float4*)&x_s[r * XS + c4 * 4] =
                *(const float4*)&x[(rbase + r) * F_IN + kh * 128 + c4 * 4];
        }
        __syncthreads();

        #pragma unroll 4
        for (int k = 0; k < 128; k++) {
            float xv[4];
            #pragma unroll
            for (int u = 0; u < 4; u++) xv[u] = x_s[(ty + 16 * u) * XS + k];
            float4 w0 = *(const float4*)&W_s[k * F_OUT + 4 * tx];
            float4 w1 = *(const float4*)&W_s[k * F_OUT + 64 + 4 * tx];
            float wv[8] = {w0.x, w0.y, w0.z, w0.w, w1.x, w1.y, w1.z, w1.w};
            #pragma unroll
            for (int u = 0; u < 4; u++)
                #pragma unroll
                for (int e = 0; e < 8; e++)
                    acc[u][e] += xv[u] * wv[e];
        }
    }

    #pragma unroll
    for (int u = 0; u < 4; u++) {
        float sa = 0.f, da = 0.f;
        #pragma unroll
        for (int e = 0; e < 8; e++) {
            sa += acc[u][e] * a1v[e];
            da += acc[u][e] * a2v[e];
        }
        #pragma unroll
        for (int o = 8; o; o >>= 1) {
            sa += __shfl_down_sync(0xffffffffu, sa, o, 16);
            da += __shfl_down_sync(0xffffffffu, da, o, 16);
        }
        const int r = rbase + ty + 16 * u;
        if (tx == 0) {
            g_src[r] = sa * LOG2E;
            g_dst[r] = da * LOG2E;
        }
    }

    __syncthreads();   // all x_s reads done
    #pragma unroll
    for (int u = 0; u < 4; u++) {
        const int col = ty + 16 * u;
        #pragma unroll
        for (int e = 0; e < 4; e++) {
            hT_tile[(4 * tx + e) * 72 + col]      = __float2half_rn(acc[u][e]);
            hT_tile[(64 + 4 * tx + e) * 72 + col] = __float2half_rn(acc[u][4 + e]);
        }
    }
    __syncthreads();
    #pragma unroll
    for (int i = 0; i < 4; i++) {
        const int idx = t + i * 256;
        const int f = idx >> 3, seg = idx & 7;
        float4 v = *(const float4*)&hT_tile[f * 72 + seg * 8];
        *(float4*)&g_hT[(size_t)f * N_NODES + rbase + seg * 8] = v;
    }
}

// ---------------------------------------------------------------------------
// Kernel 2: warp-specialized fused masked-softmax attention.
// grid 512: rb = bid>>2 (64 rows), jq = bid&3 (2048 j). block 512, 2 CTAs/SM.
// Warps 0-7: producers (scores -> double-buffered P, adj reg-prefetch).
// Warps 8-15: consumers (3-stage cp.async h pipe + fp16 MMA, warp tile 32x32,
//             ldmatrix.x4 fragment loads).
// ---------------------------------------------------------------------------
__global__ void __launch_bounds__(512, 2)
attn_kernel(const int* __restrict__ adj) {
    extern __shared__ float sm[];
    // 4B-unit layout:
    //   h2_s : 3 stages x [128 n][20 half2] -> [0, 7680)
    //   P2_s : 2 bufs   x [64 m][20 half2]  -> [7680, 10240)
    //   dst_s: [2048]                        -> [10240, 12288)
    __half2* P2_s = (__half2*)(sm + 7680);
    float*   dst_s = sm + 10240;
    const uint32_t h_u = smem_u32(sm);          // byte address of h stage 0
    const uint32_t P_u = h_u + 7680 * 4;        // byte address of P buf 0

    const int t    = threadIdx.x;
    const int rb   = blockIdx.x >> 2, jq = blockIdx.x & 3;
    const int r0   = rb * 64;
    const int jbase = jq * 2048;
    const int w    = t >> 5;

    // Stage dst for this CTA's 2048 j once (L2-hot, read many times)
    *(float4*)&dst_s[t * 4] = *(const float4*)&g_dst[jbase + t * 4];
    __syncthreads();

    if (w < 8) {
        // ================= PRODUCER =================
        const int row = t >> 2, q = t & 3;          // 64 rows x 4 groups, 8 j each
        const int* asrc = adj + (size_t)(r0 + row) * N_NODES + jbase + q * 8;
        const float srcv = g_src[r0 + row] - 4.0f;  // exponent shift folded in
        float l_reg = 0.f;

        int4 adjv[2][2];
        #pragma unroll
        for (int s = 0; s < 2; s++) {
            adjv[s][0] = *(const int4*)(asrc + s * KC);
            adjv[s][1] = *(const int4*)(asrc + s * KC + 4);
        }

        #pragma unroll 2
        for (int ch = 0; ch < NCHUNK; ch++) {
            const int slot = ch & 1;
            if (ch >= 2) BAR_SYNC(FREE0 + slot);    // consumers done with P(slot)

            __half2* Pb = P2_s + slot * 1280;
            float lsum = 0.f;
            uint4 pk;
            #pragma unroll
            for (int i = 0; i < 2; i++) {
                const int4 av = adjv[slot][i];
                const float4 dv = *(const float4*)&dst_s[ch * KC + q * 8 + i * 4];
                float s0, s1, s2, s3;
                s0 = srcv + dv.x; s0 = fmaxf(s0, 0.2f * s0 - 3.2f);
                s1 = srcv + dv.y; s1 = fmaxf(s1, 0.2f * s1 - 3.2f);
                s2 = srcv + dv.z; s2 = fmaxf(s2, 0.2f * s2 - 3.2f);
                s3 = srcv + dv.w; s3 = fmaxf(s3, 0.2f * s3 - 3.2f);
                float p0 = (av.x > 0) ? ex2(s0) : 0.f;
                float p1 = (av.y > 0) ? ex2(s1) : 0.f;
                float p2 = (av.z > 0) ? ex2(s2) : 0.f;
                float p3 = (av.w > 0) ? ex2(s3) : 0.f;
                lsum += (p0 + p1) + (p2 + p3);
                __half2 h01 = __floats2half2_rn(p0, p1);
                __half2 h23 = __floats2half2_rn(p2, p3);
                if (i == 0) { pk.x = *(uint32_t*)&h01; pk.y = *(uint32_t*)&h23; }
                else        { pk.z = *(uint32_t*)&h01; pk.w = *(uint32_t*)&h23; }
            }
            *(uint4*)&Pb[row * 20 + q * 4] = pk;

            BAR_ARRIVE(FULL0 + slot);               // P(slot) ready

            if (ch + 2 < NCHUNK) {                  // refill reg prefetch
                adjv[slot][0] = *(const int4*)(asrc + (ch + 2) * KC);
                adjv[slot][1] = *(const int4*)(asrc + (ch + 2) * KC + 4);
            }
            lsum += __shfl_xor_sync(0xffffffffu, lsum, 1, 4);
            lsum += __shfl_xor_sync(0xffffffffu, lsum, 2, 4);
            if (q == 0) l_reg += lsum;
        }
        if (q == 0) g_partL[blockIdx.x * 64 + row] = l_reg;

    } else {
        // ================= CONSUMER =================
        const int tc   = t - 256;
        const int lane = t & 31, wc = w - 8;
        const int gID  = lane >> 2, tig = lane & 3;
        const int mh   = wc & 1;                    // m-half (32 rows)
        const int nq   = wc >> 1;                   // n-quarter (32 cols)
        const int oct  = lane >> 3, ol = lane & 7;

        // per-lane ldmatrix row/segment byte offsets (row stride = 80 B)
        //  A matrices: m0..3 = (rows+0,k0)(rows+8,k0)(rows+0,k8)(rows+8,k8)
        const uint32_t a_lane = (uint32_t)((mh * 32 + ((oct & 1) << 3) + ol) * 80
                                           + ((oct >> 1) << 4));
        //  B matrices: m0..3 = (n+0,k0)(n+0,k8)(n+8,k0)(n+8,k8)
        const uint32_t b_lane = (uint32_t)((nq * 32 + ((oct >> 1) << 3) + ol) * 80
                                           + ((oct & 1) << 4));

        float acc[2][4][4];
        #pragma unroll
        for (int mt = 0; mt < 2; mt++)
            #pragma unroll
            for (int nt = 0; nt < 4; nt++)
                #pragma unroll
                for (int c = 0; c < 4; c++) acc[mt][nt][c] = 0.f;

        // h cp.async coordinates: 128 n-rows x 32 halves, 2 threads/row
        const int hn = tc >> 1, hseg = tc & 1;
        const __half* hsrc = g_hT + (size_t)hn * N_NODES + jbase + hseg * 16;
        const uint32_t hdst = h_u + (hn * 20 + hseg * 8) * 4;

        #define ISSUE_H(ch_, stoff_)                                   \
        {                                                              \
            cp16(hdst + (stoff_), hsrc + (ch_) * KC);                  \
            cp16(hdst + (stoff_) + 16, hsrc + (ch_) * KC + 8);         \
        }

        ISSUE_H(0, 0);        CP_COMMIT();
        ISSUE_H(1, 2560 * 4); CP_COMMIT();

        int st = 0;
        #pragma unroll 2
        for (int ch = 0; ch < NCHUNK; ch++) {
            const int slot = ch & 1;
            CP_WAIT1();                             // h(ch) landed (this thread)
            BAR_SYNC(FULL0 + slot);                 // P ready + h visible + peers past MMA(ch-1)

            if (ch + 2 < NCHUNK) {
                const int stn = (st + 2 >= 3) ? st - 1 : st + 2;
                ISSUE_H(ch + 2, stn * 2560 * 4);
            }
            CP_COMMIT();

            // MMA: D[64x128] += P[64x32] @ h[32x128]; warp tile 32x32
            const uint32_t Pa = P_u + slot * 5120 + a_lane;
            const uint32_t Ha = h_u + st * 10240 + b_lane;
            #pragma unroll
            for (int ks = 0; ks < 2; ks++) {
                unsigned Af[2][4];
                ldsm_x4(Af[0], Pa + ks * 32);
                ldsm_x4(Af[1], Pa + ks * 32 + 16 * 80);
                #pragma unroll
                for (int n2 = 0; n2 < 2; n2++) {
                    unsigned Bf[4];
                    ldsm_x4(Bf, Ha + ks * 32 + n2 * 16 * 80);
                    mma_f16(acc[0][2 * n2],     Af[0], Bf);
                    mma_f16(acc[0][2 * n2 + 1], Af[0], Bf + 2);
                    mma_f16(acc[1][2 * n2],     Af[1], Bf);
                    mma_f16(acc[1][2 * n2 + 1], Af[1], Bf + 2);
                }
            }

            if (ch + 2 < NCHUNK) BAR_ARRIVE(FREE0 + slot);  // P(slot) consumed
            st = (st + 1 >= 3) ? 0 : st + 1;
        }

        // Epilogue: store unnormalized partials
        const size_t dbase = (size_t)blockIdx.x * 64 * F_OUT;
        #pragma unroll
        for (int mt = 0; mt < 2; mt++) {
            const int ra = mh * 32 + mt * 16 + gID;
            #pragma unroll
            for (int nt = 0; nt < 4; nt++) {
                const int c = nq * 32 + nt * 8 + 2 * tig;
                float2 v0, v1;
                v0.x = acc[mt][nt][0]; v0.y = acc[mt][nt][1];
                v1.x = acc[mt][nt][2]; v1.y = acc[mt][nt][3];
                *(float2*)&g_partD[dbase + (size_t)ra * F_OUT + c]       = v0;
                *(float2*)&g_partD[dbase + (size_t)(ra + 8) * F_OUT + c] = v1;
            }
        }
    }
}

// ---------------------------------------------------------------------------
// Kernel 3: combine 4 j-quarters: out = sum(D_p) / sum(l_p)
// ---------------------------------------------------------------------------
__global__ void __launch_bounds__(512, 4)
combine_kernel(float* __restrict__ out) {
    const int idx  = blockIdx.x * 512 + threadIdx.x;
    const int rowc = idx >> 5;
    const int c4   = idx & 31;
    const int rbk  = rowc >> 6, m = rowc & 63;
    const size_t b0 = (size_t)(4 * rbk) * 64 * F_OUT + (size_t)m * F_OUT + c4 * 4;
    const float4 d0 = *(const float4*)&g_partD[b0];
    const float4 d1 = *(const float4*)&g_partD[b0 + 1 * 64 * F_OUT];
    const float4 d2 = *(const float4*)&g_partD[b0 + 2 * 64 * F_OUT];
    const float4 d3 = *(const float4*)&g_partD[b0 + 3 * 64 * F_OUT];
    const float lsum = g_partL[(4 * rbk + 0) * 64 + m] + g_partL[(4 * rbk + 1) * 64 + m]
                     + g_partL[(4 * rbk + 2) * 64 + m] + g_partL[(4 * rbk + 3) * 64 + m];
    const float inv = 1.f / lsum;
    float4 o;
    o.x = ((d0.x + d1.x) + (d2.x + d3.x)) * inv;
    o.y = ((d0.y + d1.y) + (d2.y + d3.y)) * inv;
    o.z = ((d0.z + d1.z) + (d2.z + d3.z)) * inv;
    o.w = ((d0.w + d1.w) + (d2.w + d3.w)) * inv;
    *(float4*)&out[(size_t)rowc * F_OUT + c4 * 4] = o;
}

// ---------------------------------------------------------------------------
extern "C" void kernel_launch(void* const* d_in, const int* in_sizes, int n_in,
                              void* d_out, int out_size) {
    const float* x   = (const float*)d_in[0];
    const int*   adj = (const int*)  d_in[1];
    const float* W   = (const float*)d_in[2];
    const float* a   = (const float*)d_in[3];
    float* out = (float*)d_out;

    const int A_SMEM = (128 * F_OUT + 64 * 132) * 4;            // 99,328 B
    const int B_SMEM = 12288 * 4;                               // 49,152 B
    cudaFuncSetAttribute(prep_kernel, cudaFuncAttributeMaxDynamicSharedMemorySize, A_SMEM);
    cudaFuncSetAttribute(attn_kernel, cudaFuncAttributeMaxDynamicSharedMemorySize, B_SMEM);

    prep_kernel<<<128, 256, A_SMEM>>>(x, W, a);
    attn_kernel<<<512, 512, B_SMEM>>>(adj);
    combine_kernel<<<512, 512>>>(out);
}